// round 2
// baseline (speedup 1.0000x reference)
#include <cuda_runtime.h>

#define Bz 64
#define Tz 512
#define Fz 512
#define Hz 1024
#define Gz 4096   // 4*H
#define NBLK 128
#define OUT_HOFF (Bz*Tz*Hz)                 // 33,554,432
#define OUT_COFF (OUT_HOFF + 2*Bz*Hz)       // + 131,072

// ---------------- static device scratch (no allocations allowed) ----------------
__device__ float g_pre[(size_t)Tz * Bz * Gz];   // [T][B][4H] input-GEMM + biases, 512MB
__device__ float g_h0[2][Bz * Hz];              // double-buffered layer0 h
__device__ float g_h1[2][Bz * Hz];              // double-buffered layer1 h
__device__ unsigned g_count;                    // grid barrier arrival counter
__device__ volatile unsigned g_sense;           // grid barrier monotonically-increasing sense

__device__ __forceinline__ float sigm(float x) { return 1.f / (1.f + __expf(-x)); }

// Grid-wide barrier. Grid=128 blocks <= SM count => all co-resident, no deadlock.
// Monotonic sense counter: re-launch safe (each launch reads current g_sense at start;
// g_count always returns to 0).
__device__ __forceinline__ void grid_bar(unsigned &sense) {
    __syncthreads();
    if (threadIdx.x == 0) {
        unsigned s = sense + 1u;
        sense = s;
        __threadfence();
        unsigned arr = atomicAdd(&g_count, 1u);
        if (arr == gridDim.x - 1) {
            g_count = 0;
            __threadfence();
            g_sense = s;
        } else {
            while (g_sense != s) { }
            __threadfence();
        }
    }
    __syncthreads();
}

// ============================================================================
// Phase A: g_pre[t][b][n] = sum_k x[b][t][k] * Wi0[n][k] + bi0[n] + bh0[n]
// GEMM M=32768 (r = t*64+b), N=4096, K=512. 128x128 tile, BK=16, 256 thr, 8x8 micro.
// ============================================================================
__global__ __launch_bounds__(256) void lstm_pre(
    const float* __restrict__ x, const float* __restrict__ Wi0,
    const float* __restrict__ bi0, const float* __restrict__ bh0)
{
    __shared__ float As[16][132];   // [k][m], padded rows (528B = 16*33, float4-aligned)
    __shared__ float Bs[16][132];   // [k][n]

    const int tid = threadIdx.x;
    const int n0 = blockIdx.x * 128;
    const int m0 = blockIdx.y * 128;
    const int ty = tid >> 4, tx = tid & 15;

    float acc[8][8];
#pragma unroll
    for (int i = 0; i < 8; i++)
#pragma unroll
        for (int j = 0; j < 8; j++) acc[i][j] = 0.f;

    for (int kc = 0; kc < Fz / 16; kc++) {
        const int k0 = kc * 16;
#pragma unroll
        for (int u = 0; u < 2; u++) {
            int idx = tid + u * 256;          // 0..511
            int row = idx >> 2, kq = idx & 3; // 128 rows x 4 float4
            // A: row r -> (t = r/64, b = r%64); x is [B][T][F]
            int r = m0 + row;
            int tt = r >> 6, bb = r & 63;
            float4 v = *(const float4*)&x[((size_t)(bb * Tz + tt)) * Fz + k0 + kq * 4];
            As[kq * 4 + 0][row] = v.x; As[kq * 4 + 1][row] = v.y;
            As[kq * 4 + 2][row] = v.z; As[kq * 4 + 3][row] = v.w;
            // B: weight row n0+row, Wi0 is [4H][F]
            float4 w = *(const float4*)&Wi0[((size_t)(n0 + row)) * Fz + k0 + kq * 4];
            Bs[kq * 4 + 0][row] = w.x; Bs[kq * 4 + 1][row] = w.y;
            Bs[kq * 4 + 2][row] = w.z; Bs[kq * 4 + 3][row] = w.w;
        }
        __syncthreads();
#pragma unroll
        for (int kk = 0; kk < 16; kk++) {
            float a[8], b[8];
            *(float4*)&a[0] = *(const float4*)&As[kk][ty * 8];
            *(float4*)&a[4] = *(const float4*)&As[kk][ty * 8 + 4];
            *(float4*)&b[0] = *(const float4*)&Bs[kk][tx * 8];
            *(float4*)&b[4] = *(const float4*)&Bs[kk][tx * 8 + 4];
#pragma unroll
            for (int i = 0; i < 8; i++)
#pragma unroll
                for (int j = 0; j < 8; j++) acc[i][j] += a[i] * b[j];
        }
        __syncthreads();
    }

    float bsv[8];
#pragma unroll
    for (int j = 0; j < 8; j++) {
        int n = n0 + tx * 8 + j;
        bsv[j] = bi0[n] + bh0[n];
    }
#pragma unroll
    for (int i = 0; i < 8; i++) {
        size_t off = (size_t)(m0 + ty * 8 + i) * Gz + n0 + tx * 8;
        float4 v0, v1;
        v0.x = acc[i][0] + bsv[0]; v0.y = acc[i][1] + bsv[1];
        v0.z = acc[i][2] + bsv[2]; v0.w = acc[i][3] + bsv[3];
        v1.x = acc[i][4] + bsv[4]; v1.y = acc[i][5] + bsv[5];
        v1.z = acc[i][6] + bsv[6]; v1.w = acc[i][7] + bsv[7];
        *(float4*)&g_pre[off]     = v0;
        *(float4*)&g_pre[off + 4] = v1;
    }
}

// ============================================================================
// Persistent recurrent kernel. Grid = 128 blocks x 256 threads.
// Block owns 8 hidden columns jbase..jbase+7 => 32 gate rows {g*H + jbase + jj}.
// Tile per block: 64 batch x 32 gate-rows; thread micro-tile: 4b x 2n.
// ============================================================================
__device__ __forceinline__ void gemm_block(
    const float* __restrict__ hsrc,     // [B][H] (K=1024 slice)
    const float* __restrict__ W,        // [4H][1024] gate-row-major
    int jbase, int b0, int ln0, int tid,
    float acc[4][2],
    float (&hs)[32][68], float (&ws)[32][36])
{
    for (int kc = 0; kc < Hz / 32; kc++) {
        const int k0 = kc * 32;
        // stage h tile [32k][64b] transposed (pad 68: conflict-free, 16B-aligned rows)
#pragma unroll
        for (int u = 0; u < 2; u++) {
            int f = tid + u * 256;          // 0..511
            int b = f >> 3, kq = f & 7;     // 64 b x 8 float4
            float4 v = *(const float4*)&hsrc[b * Hz + k0 + kq * 4];
            hs[kq * 4 + 0][b] = v.x; hs[kq * 4 + 1][b] = v.y;
            hs[kq * 4 + 2][b] = v.z; hs[kq * 4 + 3][b] = v.w;
        }
        // stage weight tile [32k][32n]
        {
            int ln = tid >> 3, kq = tid & 7;
            int row = (ln >> 3) * Hz + jbase + (ln & 7);
            float4 v = *(const float4*)&W[(size_t)row * Hz + k0 + kq * 4];
            ws[kq * 4 + 0][ln] = v.x; ws[kq * 4 + 1][ln] = v.y;
            ws[kq * 4 + 2][ln] = v.z; ws[kq * 4 + 3][ln] = v.w;
        }
        __syncthreads();
#pragma unroll
        for (int kk = 0; kk < 32; kk++) {
            float4 hv = *(const float4*)&hs[kk][b0];
            float2 wv = *(const float2*)&ws[kk][ln0];
            acc[0][0] += hv.x * wv.x; acc[0][1] += hv.x * wv.y;
            acc[1][0] += hv.y * wv.x; acc[1][1] += hv.y * wv.y;
            acc[2][0] += hv.z * wv.x; acc[2][1] += hv.z * wv.y;
            acc[3][0] += hv.w * wv.x; acc[3][1] += hv.w * wv.y;
        }
        __syncthreads();
    }
}

__global__ __launch_bounds__(256) void lstm_rec(
    const float* __restrict__ Wh0, const float* __restrict__ Wi1,
    const float* __restrict__ Wh1, const float* __restrict__ bi1,
    const float* __restrict__ bh1, float* __restrict__ out)
{
    __shared__ float hs[32][68];
    __shared__ float ws[32][36];
    __shared__ float gsm[64][33];   // gate exchange [b][ln]
    __shared__ float cs[2][512];    // cell state, [layer][b*8+jj], SMEM-resident all steps
    __shared__ float bsum1[32];

    const int tid = threadIdx.x;
    const int jbase = blockIdx.x * 8;
    const int b0  = (tid >> 4) * 4;   // 16 groups of 4 batch rows
    const int ln0 = (tid & 15) * 2;   // 16 groups of 2 gate rows
    unsigned sense = g_sense;         // safe: first write happens only after all blocks arrive

    if (tid < 32) {
        int n = (tid >> 3) * Hz + jbase + (tid & 7);
        bsum1[tid] = bi1[n] + bh1[n];
    }
#pragma unroll
    for (int u = 0; u < 4; u++) ((float*)cs)[tid + u * 256] = 0.f;
    // zero ping buffer 0 of both h states (read at t=0)
    for (int idx = blockIdx.x * 256 + tid; idx < Bz * Hz; idx += NBLK * 256) {
        g_h0[0][idx] = 0.f;
        g_h1[0][idx] = 0.f;
    }
    grid_bar(sense);

    for (int t = 0; t < Tz; t++) {
        const int rb = t & 1, wb = rb ^ 1;
        float acc[4][2];

        // ---------------- layer 0: gates = g_pre[t] + h0_prev @ Wh0^T ----------------
#pragma unroll
        for (int i = 0; i < 4; i++)
#pragma unroll
            for (int j = 0; j < 2; j++) {
                int ln = ln0 + j;
                int n = (ln >> 3) * Hz + jbase + (ln & 7);
                acc[i][j] = g_pre[((size_t)(t * Bz + b0 + i)) * Gz + n];
            }
        gemm_block(g_h0[rb], Wh0, jbase, b0, ln0, tid, acc, hs, ws);
#pragma unroll
        for (int i = 0; i < 4; i++) {
            gsm[b0 + i][ln0]     = acc[i][0];
            gsm[b0 + i][ln0 + 1] = acc[i][1];
        }
        __syncthreads();
#pragma unroll
        for (int u = 0; u < 2; u++) {
            int it = tid + u * 256;           // 0..511 = (b, jj)
            int b = it >> 3, jj = it & 7;
            float gi = gsm[b][jj],      gf = gsm[b][8 + jj];
            float gg = gsm[b][16 + jj], go = gsm[b][24 + jj];
            float c  = cs[0][it];
            float cn = sigm(gf) * c + sigm(gi) * tanhf(gg);
            float hn = sigm(go) * tanhf(cn);
            cs[0][it] = cn;
            g_h0[wb][b * Hz + jbase + jj] = hn;
            if (t == Tz - 1) {
                out[OUT_HOFF + b * Hz + jbase + jj] = hn;
                out[OUT_COFF + b * Hz + jbase + jj] = cn;
            }
        }
        grid_bar(sense);

        // ------- layer 1: gates = h0_cur @ Wi1^T + h1_prev @ Wh1^T + b1 -------
#pragma unroll
        for (int i = 0; i < 4; i++)
#pragma unroll
            for (int j = 0; j < 2; j++) acc[i][j] = bsum1[ln0 + j];
        gemm_block(g_h0[wb], Wi1, jbase, b0, ln0, tid, acc, hs, ws);  // current h0
        gemm_block(g_h1[rb], Wh1, jbase, b0, ln0, tid, acc, hs, ws);  // previous h1
#pragma unroll
        for (int i = 0; i < 4; i++) {
            gsm[b0 + i][ln0]     = acc[i][0];
            gsm[b0 + i][ln0 + 1] = acc[i][1];
        }
        __syncthreads();
#pragma unroll
        for (int u = 0; u < 2; u++) {
            int it = tid + u * 256;
            int b = it >> 3, jj = it & 7;
            float gi = gsm[b][jj],      gf = gsm[b][8 + jj];
            float gg = gsm[b][16 + jj], go = gsm[b][24 + jj];
            float c  = cs[1][it];
            float cn = sigm(gf) * c + sigm(gi) * tanhf(gg);
            float hn = sigm(go) * tanhf(cn);
            cs[1][it] = cn;
            g_h1[wb][b * Hz + jbase + jj] = hn;
            out[(size_t)(b * Tz + t) * Hz + jbase + jj] = hn;   // top-layer output
            if (t == Tz - 1) {
                out[OUT_HOFF + Bz * Hz + b * Hz + jbase + jj] = hn;
                out[OUT_COFF + Bz * Hz + b * Hz + jbase + jj] = cn;
            }
        }
        grid_bar(sense);
    }
}

// ============================================================================
extern "C" void kernel_launch(void* const* d_in, const int* in_sizes, int n_in,
                              void* d_out, int out_size)
{
    const float* x   = (const float*)d_in[0];
    const float* Wi0 = (const float*)d_in[1];
    const float* Wh0 = (const float*)d_in[2];
    const float* bi0 = (const float*)d_in[3];
    const float* bh0 = (const float*)d_in[4];
    const float* Wi1 = (const float*)d_in[5];
    const float* Wh1 = (const float*)d_in[6];
    const float* bi1 = (const float*)d_in[7];
    const float* bh1 = (const float*)d_in[8];
    float* out = (float*)d_out;

    dim3 gpre(Gz / 128, (Bz * Tz) / 128);   // (32, 256)
    lstm_pre<<<gpre, 256>>>(x, Wi0, bi0, bh0);
    lstm_rec<<<NBLK, 256>>>(Wh0, Wi1, Wh1, bi1, bh1, out);
}

// round 4
// speedup vs baseline: 1.0411x; 1.0411x over previous
#include <cuda_runtime.h>

#define Bz 64
#define Tz 512
#define Fz 512
#define Hz 1024
#define Gz 4096   // 4*H
#define NBLK 128
#define OUT_HOFF (Bz*Tz*Hz)                 // 33,554,432
#define OUT_COFF (OUT_HOFF + 2*Bz*Hz)       // + 131,072

// ---------------- static device scratch (no allocations allowed) ----------------
__device__ float g_pre[(size_t)Tz * Bz * Gz];   // [T][B][4H] input-GEMM + biases, 512MB
__device__ float g_h0[2][Bz * Hz];              // double-buffered layer0 h
__device__ float g_h1[2][Bz * Hz];              // double-buffered layer1 h
__device__ unsigned g_count;                    // grid barrier arrival counter
__device__ volatile unsigned g_sense;           // grid barrier monotonically-increasing sense

__device__ __forceinline__ float sigm(float x) { return 1.f / (1.f + __expf(-x)); }

// Grid-wide barrier. Grid=128 blocks <= SM count => all co-resident, no deadlock.
// Monotonic sense counter: re-launch safe (each launch reads current g_sense at start;
// g_count always returns to 0).
__device__ __forceinline__ void grid_bar(unsigned &sense) {
    __syncthreads();
    if (threadIdx.x == 0) {
        unsigned s = sense + 1u;
        sense = s;
        __threadfence();
        unsigned arr = atomicAdd(&g_count, 1u);
        if (arr == gridDim.x - 1) {
            g_count = 0;
            __threadfence();
            g_sense = s;
        } else {
            while (g_sense != s) { }
            __threadfence();
        }
    }
    __syncthreads();
}

// ============================================================================
// Phase A: g_pre[t][b][n] = sum_k x[b][t][k] * Wi0[n][k] + bi0[n] + bh0[n]
// GEMM M=32768 (r = t*64+b), N=4096, K=512. 128x128 tile, BK=16, 256 thr, 8x8 micro.
// ============================================================================
__global__ __launch_bounds__(256) void lstm_pre(
    const float* __restrict__ x, const float* __restrict__ Wi0,
    const float* __restrict__ bi0, const float* __restrict__ bh0)
{
    __shared__ float As[16][132];   // [k][m], padded rows (528B = 16*33, float4-aligned)
    __shared__ float Bs[16][132];   // [k][n]

    const int tid = threadIdx.x;
    const int n0 = blockIdx.x * 128;
    const int m0 = blockIdx.y * 128;
    const int ty = tid >> 4, tx = tid & 15;

    float acc[8][8];
#pragma unroll
    for (int i = 0; i < 8; i++)
#pragma unroll
        for (int j = 0; j < 8; j++) acc[i][j] = 0.f;

    for (int kc = 0; kc < Fz / 16; kc++) {
        const int k0 = kc * 16;
#pragma unroll
        for (int u = 0; u < 2; u++) {
            int idx = tid + u * 256;          // 0..511
            int row = idx >> 2, kq = idx & 3; // 128 rows x 4 float4
            // A: row r -> (t = r/64, b = r%64); x is [B][T][F]
            int r = m0 + row;
            int tt = r >> 6, bb = r & 63;
            float4 v = *(const float4*)&x[((size_t)(bb * Tz + tt)) * Fz + k0 + kq * 4];
            As[kq * 4 + 0][row] = v.x; As[kq * 4 + 1][row] = v.y;
            As[kq * 4 + 2][row] = v.z; As[kq * 4 + 3][row] = v.w;
            // B: weight row n0+row, Wi0 is [4H][F]
            float4 w = *(const float4*)&Wi0[((size_t)(n0 + row)) * Fz + k0 + kq * 4];
            Bs[kq * 4 + 0][row] = w.x; Bs[kq * 4 + 1][row] = w.y;
            Bs[kq * 4 + 2][row] = w.z; Bs[kq * 4 + 3][row] = w.w;
        }
        __syncthreads();
#pragma unroll
        for (int kk = 0; kk < 16; kk++) {
            float a[8], b[8];
            *(float4*)&a[0] = *(const float4*)&As[kk][ty * 8];
            *(float4*)&a[4] = *(const float4*)&As[kk][ty * 8 + 4];
            *(float4*)&b[0] = *(const float4*)&Bs[kk][tx * 8];
            *(float4*)&b[4] = *(const float4*)&Bs[kk][tx * 8 + 4];
#pragma unroll
            for (int i = 0; i < 8; i++)
#pragma unroll
                for (int j = 0; j < 8; j++) acc[i][j] += a[i] * b[j];
        }
        __syncthreads();
    }

    float bsv[8];
#pragma unroll
    for (int j = 0; j < 8; j++) {
        int n = n0 + tx * 8 + j;
        bsv[j] = bi0[n] + bh0[n];
    }
#pragma unroll
    for (int i = 0; i < 8; i++) {
        size_t off = (size_t)(m0 + ty * 8 + i) * Gz + n0 + tx * 8;
        float4 v0, v1;
        v0.x = acc[i][0] + bsv[0]; v0.y = acc[i][1] + bsv[1];
        v0.z = acc[i][2] + bsv[2]; v0.w = acc[i][3] + bsv[3];
        v1.x = acc[i][4] + bsv[4]; v1.y = acc[i][5] + bsv[5];
        v1.z = acc[i][6] + bsv[6]; v1.w = acc[i][7] + bsv[7];
        *(float4*)&g_pre[off]     = v0;
        *(float4*)&g_pre[off + 4] = v1;
    }
}

// ============================================================================
// Persistent recurrent kernel. Grid = 128 blocks x 256 threads.
// Block owns 8 hidden columns jbase..jbase+7 => 32 gate rows {g*H + jbase + jj}.
// Tile per block: 64 batch x 32 gate-rows; thread micro-tile: 4b x 2n.
// ============================================================================
__device__ __forceinline__ void gemm_block(
    const float* __restrict__ hsrc,     // [B][H] (K=1024 slice)
    const float* __restrict__ W,        // [4H][1024] gate-row-major
    int jbase, int b0, int ln0, int tid,
    float acc[4][2],
    float (&hs)[32][68], float (&ws)[32][36])
{
    for (int kc = 0; kc < Hz / 32; kc++) {
        const int k0 = kc * 32;
        // stage h tile [32k][64b] transposed (pad 68: conflict-free, 16B-aligned rows)
#pragma unroll
        for (int u = 0; u < 2; u++) {
            int f = tid + u * 256;          // 0..511
            int b = f >> 3, kq = f & 7;     // 64 b x 8 float4
            float4 v = *(const float4*)&hsrc[b * Hz + k0 + kq * 4];
            hs[kq * 4 + 0][b] = v.x; hs[kq * 4 + 1][b] = v.y;
            hs[kq * 4 + 2][b] = v.z; hs[kq * 4 + 3][b] = v.w;
        }
        // stage weight tile [32k][32n]
        {
            int ln = tid >> 3, kq = tid & 7;
            int row = (ln >> 3) * Hz + jbase + (ln & 7);
            float4 v = *(const float4*)&W[(size_t)row * Hz + k0 + kq * 4];
            ws[kq * 4 + 0][ln] = v.x; ws[kq * 4 + 1][ln] = v.y;
            ws[kq * 4 + 2][ln] = v.z; ws[kq * 4 + 3][ln] = v.w;
        }
        __syncthreads();
#pragma unroll
        for (int kk = 0; kk < 32; kk++) {
            float4 hv = *(const float4*)&hs[kk][b0];
            float2 wv = *(const float2*)&ws[kk][ln0];
            acc[0][0] += hv.x * wv.x; acc[0][1] += hv.x * wv.y;
            acc[1][0] += hv.y * wv.x; acc[1][1] += hv.y * wv.y;
            acc[2][0] += hv.z * wv.x; acc[2][1] += hv.z * wv.y;
            acc[3][0] += hv.w * wv.x; acc[3][1] += hv.w * wv.y;
        }
        __syncthreads();
    }
}

__global__ __launch_bounds__(256) void lstm_rec(
    const float* __restrict__ Wh0, const float* __restrict__ Wi1,
    const float* __restrict__ Wh1, const float* __restrict__ bi1,
    const float* __restrict__ bh1, float* __restrict__ out)
{
    __shared__ float hs[32][68];
    __shared__ float ws[32][36];
    __shared__ float gsm[64][33];   // gate exchange [b][ln]
    __shared__ float cs[2][512];    // cell state, [layer][b*8+jj], SMEM-resident all steps
    __shared__ float bsum1[32];

    const int tid = threadIdx.x;
    const int jbase = blockIdx.x * 8;
    const int b0  = (tid >> 4) * 4;   // 16 groups of 4 batch rows
    const int ln0 = (tid & 15) * 2;   // 16 groups of 2 gate rows
    unsigned sense = g_sense;         // safe: first write happens only after all blocks arrive

    if (tid < 32) {
        int n = (tid >> 3) * Hz + jbase + (tid & 7);
        bsum1[tid] = bi1[n] + bh1[n];
    }
#pragma unroll
    for (int u = 0; u < 4; u++) ((float*)cs)[tid + u * 256] = 0.f;
    // zero ping buffer 0 of both h states (read at t=0)
    for (int idx = blockIdx.x * 256 + tid; idx < Bz * Hz; idx += NBLK * 256) {
        g_h0[0][idx] = 0.f;
        g_h1[0][idx] = 0.f;
    }
    grid_bar(sense);

    for (int t = 0; t < Tz; t++) {
        const int rb = t & 1, wb = rb ^ 1;
        float acc[4][2];

        // ---------------- layer 0: gates = g_pre[t] + h0_prev @ Wh0^T ----------------
#pragma unroll
        for (int i = 0; i < 4; i++)
#pragma unroll
            for (int j = 0; j < 2; j++) {
                int ln = ln0 + j;
                int n = (ln >> 3) * Hz + jbase + (ln & 7);
                acc[i][j] = g_pre[((size_t)(t * Bz + b0 + i)) * Gz + n];
            }
        gemm_block(g_h0[rb], Wh0, jbase, b0, ln0, tid, acc, hs, ws);
#pragma unroll
        for (int i = 0; i < 4; i++) {
            gsm[b0 + i][ln0]     = acc[i][0];
            gsm[b0 + i][ln0 + 1] = acc[i][1];
        }
        __syncthreads();
#pragma unroll
        for (int u = 0; u < 2; u++) {
            int it = tid + u * 256;           // 0..511 = (b, jj)
            int b = it >> 3, jj = it & 7;
            float gi = gsm[b][jj],      gf = gsm[b][8 + jj];
            float gg = gsm[b][16 + jj], go = gsm[b][24 + jj];
            float c  = cs[0][it];
            float cn = sigm(gf) * c + sigm(gi) * tanhf(gg);
            float hn = sigm(go) * tanhf(cn);
            cs[0][it] = cn;
            g_h0[wb][b * Hz + jbase + jj] = hn;
            if (t == Tz - 1) {
                out[OUT_HOFF + b * Hz + jbase + jj] = hn;
                out[OUT_COFF + b * Hz + jbase + jj] = cn;
            }
        }
        grid_bar(sense);

        // ------- layer 1: gates = h0_cur @ Wi1^T + h1_prev @ Wh1^T + b1 -------
#pragma unroll
        for (int i = 0; i < 4; i++)
#pragma unroll
            for (int j = 0; j < 2; j++) acc[i][j] = bsum1[ln0 + j];
        gemm_block(g_h0[wb], Wi1, jbase, b0, ln0, tid, acc, hs, ws);  // current h0
        gemm_block(g_h1[rb], Wh1, jbase, b0, ln0, tid, acc, hs, ws);  // previous h1
#pragma unroll
        for (int i = 0; i < 4; i++) {
            gsm[b0 + i][ln0]     = acc[i][0];
            gsm[b0 + i][ln0 + 1] = acc[i][1];
        }
        __syncthreads();
#pragma unroll
        for (int u = 0; u < 2; u++) {
            int it = tid + u * 256;
            int b = it >> 3, jj = it & 7;
            float gi = gsm[b][jj],      gf = gsm[b][8 + jj];
            float gg = gsm[b][16 + jj], go = gsm[b][24 + jj];
            float c  = cs[1][it];
            float cn = sigm(gf) * c + sigm(gi) * tanhf(gg);
            float hn = sigm(go) * tanhf(cn);
            cs[1][it] = cn;
            g_h1[wb][b * Hz + jbase + jj] = hn;
            out[(size_t)(b * Tz + t) * Hz + jbase + jj] = hn;   // top-layer output
            if (t == Tz - 1) {
                out[OUT_HOFF + Bz * Hz + b * Hz + jbase + jj] = hn;
                out[OUT_COFF + Bz * Hz + b * Hz + jbase + jj] = cn;
            }
        }
        grid_bar(sense);
    }
}

// ============================================================================
extern "C" void kernel_launch(void* const* d_in, const int* in_sizes, int n_in,
                              void* d_out, int out_size)
{
    const float* x   = (const float*)d_in[0];
    const float* Wi0 = (const float*)d_in[1];
    const float* Wh0 = (const float*)d_in[2];
    const float* bi0 = (const float*)d_in[3];
    const float* bh0 = (const float*)d_in[4];
    const float* Wi1 = (const float*)d_in[5];
    const float* Wh1 = (const float*)d_in[6];
    const float* bi1 = (const float*)d_in[7];
    const float* bh1 = (const float*)d_in[8];
    float* out = (float*)d_out;

    dim3 gpre(Gz / 128, (Bz * Tz) / 128);   // (32, 256)
    lstm_pre<<<gpre, 256>>>(x, Wi0, bi0, bh0);
    lstm_rec<<<NBLK, 256>>>(Wh0, Wi1, Wh1, bi1, bh1, out);
}

// round 7
// speedup vs baseline: 1.2537x; 1.2042x over previous
#include <cuda_runtime.h>

#define Bz 64
#define Tz 512
#define Fz 512
#define Hz 1024
#define Gz 4096   // 4*H
#define NBLK 128
#define OUT_HOFF (Bz*Tz*Hz)                 // 33,554,432
#define OUT_COFF (OUT_HOFF + 2*Bz*Hz)       // + 131,072

typedef unsigned long long ull;

// ---------------- static device scratch (no allocations allowed) ----------------
__device__ float g_pre[(size_t)Tz * Bz * Gz];   // [T][B][4H] input-GEMM + biases, 512MB
__device__ float g_h0[2][Bz * Hz];              // double-buffered layer0 h
__device__ float g_h1[2][Bz * Hz];              // double-buffered layer1 h
__device__ unsigned g_count;                    // grid barrier arrival counter
__device__ volatile unsigned g_sense;           // grid barrier monotonically-increasing sense

__device__ __forceinline__ float sigm(float x) { return 1.f / (1.f + __expf(-x)); }

// ---- packed fp32x2 FMA (sm_10x FFMA2; only reachable via PTX) ----
__device__ __forceinline__ void ffma2(ull &d, ull a, ull b) {
    asm("fma.rn.f32x2 %0, %1, %2, %0;" : "+l"(d) : "l"(a), "l"(b));
}
__device__ __forceinline__ ull pack2(float x, float y) {
    ull r; asm("mov.b64 %0, {%1, %2};" : "=l"(r) : "f"(x), "f"(y)); return r;
}
__device__ __forceinline__ ull dup2(float x) { return pack2(x, x); }
__device__ __forceinline__ float2 unpack2(ull v) {
    float2 r; asm("mov.b64 {%0, %1}, %2;" : "=f"(r.x), "=f"(r.y) : "l"(v)); return r;
}

// Grid-wide barrier. Grid=128 blocks <= SM count => all co-resident, no deadlock.
__device__ __forceinline__ void grid_bar(unsigned &sense) {
    __syncthreads();
    if (threadIdx.x == 0) {
        unsigned s = sense + 1u;
        sense = s;
        __threadfence();
        unsigned arr = atomicAdd(&g_count, 1u);
        if (arr == gridDim.x - 1) {
            g_count = 0;
            __threadfence();
            g_sense = s;
        } else {
            while (g_sense != s) { }
            __threadfence();
        }
    }
    __syncthreads();
}

// ============================================================================
// Phase A: g_pre[t][b][n] = sum_k x[b][t][k] * Wi0[n][k] + bi0[n] + bh0[n]
// GEMM M=32768, N=4096, K=512. 128x128 tile, BK=16, 256 thr, 8x8 micro.
// f32x2 accumulators (4 b-pairs x 8 n) + register-double-buffered staging.
// ============================================================================
__global__ __launch_bounds__(256) void lstm_pre(
    const float* __restrict__ x, const float* __restrict__ Wi0,
    const float* __restrict__ bi0, const float* __restrict__ bh0)
{
    __shared__ float As[16][132];   // [k][m], padded rows (528B, float4-aligned)
    __shared__ float Bs[16][132];   // [k][n]

    const int tid = threadIdx.x;
    const int n0 = blockIdx.x * 128;
    const int m0 = blockIdx.y * 128;
    const int ty = tid >> 4, tx = tid & 15;

    // staging slots: 512 float4 loads, 2 per thread
    const int r0 = tid >> 2,          kq0 = tid & 3;
    const int r1 = (tid + 256) >> 2,  kq1 = (tid + 256) & 3;
    const int gr0 = m0 + r0, gr1 = m0 + r1;
    // A row r -> (t = r/64, b = r%64); x is [B][T][F]
    const float* xa0 = &x[((size_t)((gr0 & 63) * Tz + (gr0 >> 6))) * Fz + kq0 * 4];
    const float* xa1 = &x[((size_t)((gr1 & 63) * Tz + (gr1 >> 6))) * Fz + kq1 * 4];
    const float* wb0 = &Wi0[((size_t)(n0 + r0)) * Fz + kq0 * 4];
    const float* wb1 = &Wi0[((size_t)(n0 + r1)) * Fz + kq1 * 4];

    ull acc2[4][8];
#pragma unroll
    for (int p = 0; p < 4; p++)
#pragma unroll
        for (int j = 0; j < 8; j++) acc2[p][j] = 0ull;

    float4 pa0 = *(const float4*)xa0;
    float4 pa1 = *(const float4*)xa1;
    float4 pb0 = *(const float4*)wb0;
    float4 pb1 = *(const float4*)wb1;

    for (int kc = 0; kc < Fz / 16; kc++) {
        __syncthreads();    // previous tile's compute done
        As[kq0 * 4 + 0][r0] = pa0.x; As[kq0 * 4 + 1][r0] = pa0.y;
        As[kq0 * 4 + 2][r0] = pa0.z; As[kq0 * 4 + 3][r0] = pa0.w;
        As[kq1 * 4 + 0][r1] = pa1.x; As[kq1 * 4 + 1][r1] = pa1.y;
        As[kq1 * 4 + 2][r1] = pa1.z; As[kq1 * 4 + 3][r1] = pa1.w;
        Bs[kq0 * 4 + 0][r0] = pb0.x; Bs[kq0 * 4 + 1][r0] = pb0.y;
        Bs[kq0 * 4 + 2][r0] = pb0.z; Bs[kq0 * 4 + 3][r0] = pb0.w;
        Bs[kq1 * 4 + 0][r1] = pb1.x; Bs[kq1 * 4 + 1][r1] = pb1.y;
        Bs[kq1 * 4 + 2][r1] = pb1.z; Bs[kq1 * 4 + 3][r1] = pb1.w;
        __syncthreads();
        if (kc < Fz / 16 - 1) {     // prefetch next tile (latency overlaps compute)
            int off = (kc + 1) * 16;
            pa0 = *(const float4*)(xa0 + off);
            pa1 = *(const float4*)(xa1 + off);
            pb0 = *(const float4*)(wb0 + off);
            pb1 = *(const float4*)(wb1 + off);
        }
#pragma unroll
        for (int kk = 0; kk < 16; kk++) {
            ulonglong2 a01 = *(const ulonglong2*)&As[kk][ty * 8];      // b-pairs (0,1),(2,3)
            ulonglong2 a23 = *(const ulonglong2*)&As[kk][ty * 8 + 4];  // b-pairs (4,5),(6,7)
            float bb[8];
            *(float4*)&bb[0] = *(const float4*)&Bs[kk][tx * 8];
            *(float4*)&bb[4] = *(const float4*)&Bs[kk][tx * 8 + 4];
#pragma unroll
            for (int j = 0; j < 8; j++) {
                ull wd = dup2(bb[j]);
                ffma2(acc2[0][j], a01.x, wd);
                ffma2(acc2[1][j], a01.y, wd);
                ffma2(acc2[2][j], a23.x, wd);
                ffma2(acc2[3][j], a23.y, wd);
            }
        }
    }

    float accf[8][8];
#pragma unroll
    for (int p = 0; p < 4; p++)
#pragma unroll
        for (int j = 0; j < 8; j++) {
            float2 v = unpack2(acc2[p][j]);
            accf[2 * p][j] = v.x;
            accf[2 * p + 1][j] = v.y;
        }

    float bsv[8];
#pragma unroll
    for (int j = 0; j < 8; j++) {
        int n = n0 + tx * 8 + j;
        bsv[j] = bi0[n] + bh0[n];
    }
#pragma unroll
    for (int i = 0; i < 8; i++) {
        size_t off = (size_t)(m0 + ty * 8 + i) * Gz + n0 + tx * 8;
        float4 v0, v1;
        v0.x = accf[i][0] + bsv[0]; v0.y = accf[i][1] + bsv[1];
        v0.z = accf[i][2] + bsv[2]; v0.w = accf[i][3] + bsv[3];
        v1.x = accf[i][4] + bsv[4]; v1.y = accf[i][5] + bsv[5];
        v1.z = accf[i][6] + bsv[6]; v1.w = accf[i][7] + bsv[7];
        *(float4*)&g_pre[off]     = v0;
        *(float4*)&g_pre[off + 4] = v1;
    }
}

// ============================================================================
// Persistent recurrent kernel. Grid = 128 blocks x 256 threads.
// Block owns 8 hidden cols => 32 gate rows; tile 64b x 32n; micro 4b x 2n,
// batch-paired into f32x2 accumulators (2 pairs x 2 n). Double-buffered staging.
// ============================================================================
__device__ __forceinline__ void gemm_block(
    const float* __restrict__ hsrc,     // [B][H] (K=1024 slice)
    const float* __restrict__ W,        // [4H][1024] gate-row-major
    int jbase, int b0, int ln0, int tid,
    ull acc[2][2],
    float (&hs)[32][68], float (&ws)[32][36])
{
    // staging addresses (h: 512 float4 => 2/thread; w: 256 float4 => 1/thread)
    const int hb0 = tid >> 3,         hk0 = tid & 7;
    const int hb1 = (tid + 256) >> 3, hk1 = (tid + 256) & 7;
    const int wln = tid >> 3,         wkq = tid & 7;
    const int wrow = (wln >> 3) * Hz + jbase + (wln & 7);
    const float* hp0 = &hsrc[hb0 * Hz + hk0 * 4];
    const float* hp1 = &hsrc[hb1 * Hz + hk1 * 4];
    const float* wp  = &W[(size_t)wrow * Hz + wkq * 4];

    float4 ph0 = *(const float4*)hp0;
    float4 ph1 = *(const float4*)hp1;
    float4 pw  = *(const float4*)wp;

    for (int kc = 0; kc < Hz / 32; kc++) {
        __syncthreads();    // previous tile fully consumed
        hs[hk0 * 4 + 0][hb0] = ph0.x; hs[hk0 * 4 + 1][hb0] = ph0.y;
        hs[hk0 * 4 + 2][hb0] = ph0.z; hs[hk0 * 4 + 3][hb0] = ph0.w;
        hs[hk1 * 4 + 0][hb1] = ph1.x; hs[hk1 * 4 + 1][hb1] = ph1.y;
        hs[hk1 * 4 + 2][hb1] = ph1.z; hs[hk1 * 4 + 3][hb1] = ph1.w;
        ws[wkq * 4 + 0][wln] = pw.x;  ws[wkq * 4 + 1][wln] = pw.y;
        ws[wkq * 4 + 2][wln] = pw.z;  ws[wkq * 4 + 3][wln] = pw.w;
        __syncthreads();
        if (kc < Hz / 32 - 1) {     // prefetch next tile into regs
            int off = (kc + 1) * 32;
            ph0 = *(const float4*)(hp0 + off);
            ph1 = *(const float4*)(hp1 + off);
            pw  = *(const float4*)(wp + off);
        }
#pragma unroll
        for (int kk = 0; kk < 32; kk++) {
            ulonglong2 hv = *(const ulonglong2*)&hs[kk][b0];  // b-pairs (b0,b0+1),(b0+2,b0+3)
            float2 wv = *(const float2*)&ws[kk][ln0];
            ull w0 = dup2(wv.x), w1 = dup2(wv.y);
            ffma2(acc[0][0], hv.x, w0);
            ffma2(acc[1][0], hv.y, w0);
            ffma2(acc[0][1], hv.x, w1);
            ffma2(acc[1][1], hv.y, w1);
        }
    }
}

__global__ __launch_bounds__(256) void lstm_rec(
    const float* __restrict__ Wh0, const float* __restrict__ Wi1,
    const float* __restrict__ Wh1, const float* __restrict__ bi1,
    const float* __restrict__ bh1, float* __restrict__ out)
{
    __shared__ float hs[32][68];
    __shared__ float ws[32][36];
    __shared__ float gsm[64][33];   // gate exchange [b][ln]
    __shared__ float cs[2][512];    // cell state, SMEM-resident all steps
    __shared__ float bsum1[32];

    const int tid = threadIdx.x;
    const int jbase = blockIdx.x * 8;
    const int b0  = (tid >> 4) * 4;   // 16 groups of 4 batch rows
    const int ln0 = (tid & 15) * 2;   // 16 groups of 2 gate rows
    unsigned sense = g_sense;

    if (tid < 32) {
        int n = (tid >> 3) * Hz + jbase + (tid & 7);
        bsum1[tid] = bi1[n] + bh1[n];
    }
#pragma unroll
    for (int u = 0; u < 4; u++) ((float*)cs)[tid + u * 256] = 0.f;
    for (int idx = blockIdx.x * 256 + tid; idx < Bz * Hz; idx += NBLK * 256) {
        g_h0[0][idx] = 0.f;
        g_h1[0][idx] = 0.f;
    }
    grid_bar(sense);

    for (int t = 0; t < Tz; t++) {
        const int rb = t & 1, wb = rb ^ 1;
        ull acc[2][2];

        // ---------------- layer 0: gates = g_pre[t] + h0_prev @ Wh0^T ----------------
        {
            const float* pre = &g_pre[(size_t)(t * Bz) * Gz];
#pragma unroll
            for (int j = 0; j < 2; j++) {
                int ln = ln0 + j;
                int n = (ln >> 3) * Hz + jbase + (ln & 7);
#pragma unroll
                for (int bp = 0; bp < 2; bp++) {
                    float lo = pre[(size_t)(b0 + 2 * bp) * Gz + n];
                    float hi = pre[(size_t)(b0 + 2 * bp + 1) * Gz + n];
                    acc[bp][j] = pack2(lo, hi);
                }
            }
        }
        gemm_block(g_h0[rb], Wh0, jbase, b0, ln0, tid, acc, hs, ws);
#pragma unroll
        for (int bp = 0; bp < 2; bp++)
#pragma unroll
            for (int j = 0; j < 2; j++) {
                float2 v = unpack2(acc[bp][j]);
                gsm[b0 + 2 * bp][ln0 + j]     = v.x;
                gsm[b0 + 2 * bp + 1][ln0 + j] = v.y;
            }
        __syncthreads();
#pragma unroll
        for (int u = 0; u < 2; u++) {
            int it = tid + u * 256;           // 0..511 = (b, jj)
            int b = it >> 3, jj = it & 7;
            float gi = gsm[b][jj],      gf = gsm[b][8 + jj];
            float gg = gsm[b][16 + jj], go = gsm[b][24 + jj];
            float c  = cs[0][it];
            float cn = sigm(gf) * c + sigm(gi) * tanhf(gg);
            float hn = sigm(go) * tanhf(cn);
            cs[0][it] = cn;
            g_h0[wb][b * Hz + jbase + jj] = hn;
            if (t == Tz - 1) {
                out[OUT_HOFF + b * Hz + jbase + jj] = hn;
                out[OUT_COFF + b * Hz + jbase + jj] = cn;
            }
        }
        grid_bar(sense);

        // ------- layer 1: gates = h0_cur @ Wi1^T + h1_prev @ Wh1^T + b1 -------
#pragma unroll
        for (int j = 0; j < 2; j++) {
            ull bv = dup2(bsum1[ln0 + j]);
            acc[0][j] = bv;
            acc[1][j] = bv;
        }
        gemm_block(g_h0[wb], Wi1, jbase, b0, ln0, tid, acc, hs, ws);  // current h0
        gemm_block(g_h1[rb], Wh1, jbase, b0, ln0, tid, acc, hs, ws);  // previous h1
#pragma unroll
        for (int bp = 0; bp < 2; bp++)
#pragma unroll
            for (int j = 0; j < 2; j++) {
                float2 v = unpack2(acc[bp][j]);
                gsm[b0 + 2 * bp][ln0 + j]     = v.x;
                gsm[b0 + 2 * bp + 1][ln0 + j] = v.y;
            }
        __syncthreads();
#pragma unroll
        for (int u = 0; u < 2; u++) {
            int it = tid + u * 256;
            int b = it >> 3, jj = it & 7;
            float gi = gsm[b][jj],      gf = gsm[b][8 + jj];
            float gg = gsm[b][16 + jj], go = gsm[b][24 + jj];
            float c  = cs[1][it];
            float cn = sigm(gf) * c + sigm(gi) * tanhf(gg);
            float hn = sigm(go) * tanhf(cn);
            cs[1][it] = cn;
            g_h1[wb][b * Hz + jbase + jj] = hn;
            out[(size_t)(b * Tz + t) * Hz + jbase + jj] = hn;   // top-layer output
            if (t == Tz - 1) {
                out[OUT_HOFF + Bz * Hz + b * Hz + jbase + jj] = hn;
                out[OUT_COFF + Bz * Hz + b * Hz + jbase + jj] = cn;
            }
        }
        grid_bar(sense);
    }
}

// ============================================================================
extern "C" void kernel_launch(void* const* d_in, const int* in_sizes, int n_in,
                              void* d_out, int out_size)
{
    const float* x   = (const float*)d_in[0];
    const float* Wi0 = (const float*)d_in[1];
    const float* Wh0 = (const float*)d_in[2];
    const float* bi0 = (const float*)d_in[3];
    const float* bh0 = (const float*)d_in[4];
    const float* Wi1 = (const float*)d_in[5];
    const float* Wh1 = (const float*)d_in[6];
    const float* bi1 = (const float*)d_in[7];
    const float* bh1 = (const float*)d_in[8];
    float* out = (float*)d_out;

    dim3 gpre(Gz / 128, (Bz * Tz) / 128);   // (32, 256)
    lstm_pre<<<gpre, 256>>>(x, Wi0, bi0, bh0);
    lstm_rec<<<NBLK, 256>>>(Wh0, Wi1, Wh1, bi1, bh1, out);
}

// round 8
// speedup vs baseline: 1.3161x; 1.0498x over previous
#include <cuda_runtime.h>

#define Bz 64
#define Tz 512
#define Fz 512
#define Hz 1024
#define Gz 4096   // 4*H
#define NBLK 128
#define OUT_HOFF (Bz*Tz*Hz)                 // 33,554,432
#define OUT_COFF (OUT_HOFF + 2*Bz*Hz)       // + 131,072

typedef unsigned long long ull;

// ---------------- static device scratch (no allocations allowed) ----------------
__device__ float g_pre[(size_t)Tz * Bz * Gz];   // [T][B][4H] input-GEMM + biases, 512MB
__device__ float g_h0[2][Bz * Hz];              // double-buffered layer0 h
__device__ float g_h1[2][Bz * Hz];              // double-buffered layer1 h
__device__ unsigned g_count;                    // grid barrier arrival counter
__device__ volatile unsigned g_sense;           // grid barrier monotonically-increasing sense

__device__ __forceinline__ float sigm(float x) { return 1.f / (1.f + __expf(-x)); }

// ---- packed fp32x2 FMA (sm_10x FFMA2; only reachable via PTX) ----
__device__ __forceinline__ void ffma2(ull &d, ull a, ull b) {
    asm("fma.rn.f32x2 %0, %1, %2, %0;" : "+l"(d) : "l"(a), "l"(b));
}
__device__ __forceinline__ ull pack2(float x, float y) {
    ull r; asm("mov.b64 %0, {%1, %2};" : "=l"(r) : "f"(x), "f"(y)); return r;
}
__device__ __forceinline__ ull dup2(float x) { return pack2(x, x); }
__device__ __forceinline__ float2 unpack2(ull v) {
    float2 r; asm("mov.b64 {%0, %1}, %2;" : "=f"(r.x), "=f"(r.y) : "l"(v)); return r;
}

// Grid-wide barrier. Grid=128 blocks <= SM count => all co-resident, no deadlock.
__device__ __forceinline__ void grid_bar(unsigned &sense) {
    __syncthreads();
    if (threadIdx.x == 0) {
        unsigned s = sense + 1u;
        sense = s;
        __threadfence();
        unsigned arr = atomicAdd(&g_count, 1u);
        if (arr == gridDim.x - 1) {
            g_count = 0;
            __threadfence();
            g_sense = s;
        } else {
            while (g_sense != s) { }
            __threadfence();
        }
    }
    __syncthreads();
}

// ============================================================================
// Phase A: g_pre[t][b][n] = sum_k x[b][t][k] * Wi0[n][k] + bi0[n] + bh0[n]
// (unchanged from R4 — ~2.5ms, not the bottleneck)
// ============================================================================
__global__ __launch_bounds__(256) void lstm_pre(
    const float* __restrict__ x, const float* __restrict__ Wi0,
    const float* __restrict__ bi0, const float* __restrict__ bh0)
{
    __shared__ float As[16][132];
    __shared__ float Bs[16][132];

    const int tid = threadIdx.x;
    const int n0 = blockIdx.x * 128;
    const int m0 = blockIdx.y * 128;
    const int ty = tid >> 4, tx = tid & 15;

    const int r0 = tid >> 2,          kq0 = tid & 3;
    const int r1 = (tid + 256) >> 2,  kq1 = (tid + 256) & 3;
    const int gr0 = m0 + r0, gr1 = m0 + r1;
    const float* xa0 = &x[((size_t)((gr0 & 63) * Tz + (gr0 >> 6))) * Fz + kq0 * 4];
    const float* xa1 = &x[((size_t)((gr1 & 63) * Tz + (gr1 >> 6))) * Fz + kq1 * 4];
    const float* wb0 = &Wi0[((size_t)(n0 + r0)) * Fz + kq0 * 4];
    const float* wb1 = &Wi0[((size_t)(n0 + r1)) * Fz + kq1 * 4];

    ull acc2[4][8];
#pragma unroll
    for (int p = 0; p < 4; p++)
#pragma unroll
        for (int j = 0; j < 8; j++) acc2[p][j] = 0ull;

    float4 pa0 = *(const float4*)xa0;
    float4 pa1 = *(const float4*)xa1;
    float4 pb0 = *(const float4*)wb0;
    float4 pb1 = *(const float4*)wb1;

    for (int kc = 0; kc < Fz / 16; kc++) {
        __syncthreads();
        As[kq0 * 4 + 0][r0] = pa0.x; As[kq0 * 4 + 1][r0] = pa0.y;
        As[kq0 * 4 + 2][r0] = pa0.z; As[kq0 * 4 + 3][r0] = pa0.w;
        As[kq1 * 4 + 0][r1] = pa1.x; As[kq1 * 4 + 1][r1] = pa1.y;
        As[kq1 * 4 + 2][r1] = pa1.z; As[kq1 * 4 + 3][r1] = pa1.w;
        Bs[kq0 * 4 + 0][r0] = pb0.x; Bs[kq0 * 4 + 1][r0] = pb0.y;
        Bs[kq0 * 4 + 2][r0] = pb0.z; Bs[kq0 * 4 + 3][r0] = pb0.w;
        Bs[kq1 * 4 + 0][r1] = pb1.x; Bs[kq1 * 4 + 1][r1] = pb1.y;
        Bs[kq1 * 4 + 2][r1] = pb1.z; Bs[kq1 * 4 + 3][r1] = pb1.w;
        __syncthreads();
        if (kc < Fz / 16 - 1) {
            int off = (kc + 1) * 16;
            pa0 = *(const float4*)(xa0 + off);
            pa1 = *(const float4*)(xa1 + off);
            pb0 = *(const float4*)(wb0 + off);
            pb1 = *(const float4*)(wb1 + off);
        }
#pragma unroll
        for (int kk = 0; kk < 16; kk++) {
            ulonglong2 a01 = *(const ulonglong2*)&As[kk][ty * 8];
            ulonglong2 a23 = *(const ulonglong2*)&As[kk][ty * 8 + 4];
            float bb[8];
            *(float4*)&bb[0] = *(const float4*)&Bs[kk][tx * 8];
            *(float4*)&bb[4] = *(const float4*)&Bs[kk][tx * 8 + 4];
#pragma unroll
            for (int j = 0; j < 8; j++) {
                ull wd = dup2(bb[j]);
                ffma2(acc2[0][j], a01.x, wd);
                ffma2(acc2[1][j], a01.y, wd);
                ffma2(acc2[2][j], a23.x, wd);
                ffma2(acc2[3][j], a23.y, wd);
            }
        }
    }

    float accf[8][8];
#pragma unroll
    for (int p = 0; p < 4; p++)
#pragma unroll
        for (int j = 0; j < 8; j++) {
            float2 v = unpack2(acc2[p][j]);
            accf[2 * p][j] = v.x;
            accf[2 * p + 1][j] = v.y;
        }

    float bsv[8];
#pragma unroll
    for (int j = 0; j < 8; j++) {
        int n = n0 + tx * 8 + j;
        bsv[j] = bi0[n] + bh0[n];
    }
#pragma unroll
    for (int i = 0; i < 8; i++) {
        size_t off = (size_t)(m0 + ty * 8 + i) * Gz + n0 + tx * 8;
        float4 v0, v1;
        v0.x = accf[i][0] + bsv[0]; v0.y = accf[i][1] + bsv[1];
        v0.z = accf[i][2] + bsv[2]; v0.w = accf[i][3] + bsv[3];
        v1.x = accf[i][4] + bsv[4]; v1.y = accf[i][5] + bsv[5];
        v1.z = accf[i][6] + bsv[6]; v1.w = accf[i][7] + bsv[7];
        *(float4*)&g_pre[off]     = v0;
        *(float4*)&g_pre[off + 4] = v1;
    }
}

// ============================================================================
// Persistent recurrent kernel, K-SPLIT version.
// 256 threads = 4 k-groups x 64 threads. Each group: 64b x 32n tile over its
// K/4=256 slice with an 8b x 4n micro-tile (f32x2: acc[4 b-pairs][4 n]).
// SMEM bytes per FMA: 48B / 32 FMA = 1.5 (was 3.0). Partials reduced in SMEM.
// ============================================================================

// SMEM pool layout (floats), regions are a union:
//   tiles:  hs[grp] at grp*1088 (16k x 68), ws[grp] at 4352 + grp*576 (16k x 36)
//   parts:  grp g>=1 partial at (g-1)*2304 ([64][36]); grp 0 goes to gsm
#define HS_OFF(g)  ((g) * 1088)
#define WS_OFF(g)  (4352 + (g) * 576)
#define PART_OFF(g) (((g) - 1) * 2304)

__device__ __forceinline__ void gemm_ks(
    const float* __restrict__ hsrc,     // [B][H]
    const float* __restrict__ W,        // [4H][H] gate-row-major
    int jbase, int wtid, int kbase, ull (&acc)[4][4],
    float* __restrict__ hs, float* __restrict__ ws)
{
    const int b0  = (wtid >> 3) * 8;
    const int ln0 = (wtid & 7) * 4;

    // h staging: thread owns batch row b=wtid, loads 64 contiguous bytes (16 k) per iter
    const float* hp = hsrc + (size_t)wtid * Hz + kbase;
    // w staging: 2 slots; idx = wtid + s*64 -> ln = idx>>2, kq = idx&3 (64B contiguous per row)
    const float* wp[2];
    int wln[2], wkq[2];
#pragma unroll
    for (int s = 0; s < 2; s++) {
        int idx = wtid + s * 64;
        wln[s] = idx >> 2; wkq[s] = idx & 3;
        int row = (wln[s] >> 3) * Hz + jbase + (wln[s] & 7);
        wp[s] = W + (size_t)row * Hz + kbase + wkq[s] * 4;
    }

    float4 ph0 = *(const float4*)(hp);
    float4 ph1 = *(const float4*)(hp + 4);
    float4 ph2 = *(const float4*)(hp + 8);
    float4 ph3 = *(const float4*)(hp + 12);
    float4 pw0 = *(const float4*)wp[0];
    float4 pw1 = *(const float4*)wp[1];

    for (int kc = 0; kc < 16; kc++) {
        __syncthreads();        // previous tile fully consumed
        hs[ 0 * 68 + wtid] = ph0.x; hs[ 1 * 68 + wtid] = ph0.y;
        hs[ 2 * 68 + wtid] = ph0.z; hs[ 3 * 68 + wtid] = ph0.w;
        hs[ 4 * 68 + wtid] = ph1.x; hs[ 5 * 68 + wtid] = ph1.y;
        hs[ 6 * 68 + wtid] = ph1.z; hs[ 7 * 68 + wtid] = ph1.w;
        hs[ 8 * 68 + wtid] = ph2.x; hs[ 9 * 68 + wtid] = ph2.y;
        hs[10 * 68 + wtid] = ph2.z; hs[11 * 68 + wtid] = ph2.w;
        hs[12 * 68 + wtid] = ph3.x; hs[13 * 68 + wtid] = ph3.y;
        hs[14 * 68 + wtid] = ph3.z; hs[15 * 68 + wtid] = ph3.w;
        ws[(wkq[0] * 4 + 0) * 36 + wln[0]] = pw0.x;
        ws[(wkq[0] * 4 + 1) * 36 + wln[0]] = pw0.y;
        ws[(wkq[0] * 4 + 2) * 36 + wln[0]] = pw0.z;
        ws[(wkq[0] * 4 + 3) * 36 + wln[0]] = pw0.w;
        ws[(wkq[1] * 4 + 0) * 36 + wln[1]] = pw1.x;
        ws[(wkq[1] * 4 + 1) * 36 + wln[1]] = pw1.y;
        ws[(wkq[1] * 4 + 2) * 36 + wln[1]] = pw1.z;
        ws[(wkq[1] * 4 + 3) * 36 + wln[1]] = pw1.w;
        __syncthreads();
        if (kc < 15) {          // prefetch next tile into regs (overlaps compute)
            int off = (kc + 1) * 16;
            ph0 = *(const float4*)(hp + off);
            ph1 = *(const float4*)(hp + off + 4);
            ph2 = *(const float4*)(hp + off + 8);
            ph3 = *(const float4*)(hp + off + 12);
            pw0 = *(const float4*)(wp[0] + off);
            pw1 = *(const float4*)(wp[1] + off);
        }
#pragma unroll 4
        for (int kk = 0; kk < 16; kk++) {
            const float* hrow = hs + kk * 68 + b0;
            ulonglong2 hA = *(const ulonglong2*)(hrow);      // b-pairs (0,1),(2,3)
            ulonglong2 hB = *(const ulonglong2*)(hrow + 4);  // b-pairs (4,5),(6,7)
            float4 wv = *(const float4*)(ws + kk * 36 + ln0);
            ull w0 = dup2(wv.x), w1 = dup2(wv.y), w2 = dup2(wv.z), w3 = dup2(wv.w);
            ffma2(acc[0][0], hA.x, w0); ffma2(acc[1][0], hA.y, w0);
            ffma2(acc[2][0], hB.x, w0); ffma2(acc[3][0], hB.y, w0);
            ffma2(acc[0][1], hA.x, w1); ffma2(acc[1][1], hA.y, w1);
            ffma2(acc[2][1], hB.x, w1); ffma2(acc[3][1], hB.y, w1);
            ffma2(acc[0][2], hA.x, w2); ffma2(acc[1][2], hA.y, w2);
            ffma2(acc[2][2], hB.x, w2); ffma2(acc[3][2], hB.y, w2);
            ffma2(acc[0][3], hA.x, w3); ffma2(acc[1][3], hA.y, w3);
            ffma2(acc[2][3], hB.x, w3); ffma2(acc[3][3], hB.y, w3);
        }
    }
}

// Unpack f32x2 accumulators into a [64][36] partial buffer (float4 rows).
__device__ __forceinline__ void store_part(float* __restrict__ dst,
                                           int b0, int ln0, ull (&acc)[4][4])
{
#pragma unroll
    for (int bp = 0; bp < 4; bp++) {
        float2 v0 = unpack2(acc[bp][0]);
        float2 v1 = unpack2(acc[bp][1]);
        float2 v2 = unpack2(acc[bp][2]);
        float2 v3 = unpack2(acc[bp][3]);
        float4 lo, hi;
        lo.x = v0.x; lo.y = v1.x; lo.z = v2.x; lo.w = v3.x;
        hi.x = v0.y; hi.y = v1.y; hi.z = v2.y; hi.w = v3.y;
        *(float4*)&dst[(b0 + 2 * bp) * 36 + ln0]     = lo;
        *(float4*)&dst[(b0 + 2 * bp + 1) * 36 + ln0] = hi;
    }
}

__global__ __launch_bounds__(256) void lstm_rec(
    const float* __restrict__ Wh0, const float* __restrict__ Wi1,
    const float* __restrict__ Wh1, const float* __restrict__ bi1,
    const float* __restrict__ bh1, float* __restrict__ out)
{
    __shared__ __align__(16) float pool[6912];      // tiles / partials union
    __shared__ __align__(16) float gsm[64 * 36];    // grp0 partial + reduced gates
    __shared__ float cs[2][512];                    // cell state
    __shared__ float bsum1[32];

    const int tid = threadIdx.x;
    const int jbase = blockIdx.x * 8;
    const int kgrp = tid >> 6;
    const int wtid = tid & 63;
    const int kbase = kgrp * 256;
    const int b0  = (wtid >> 3) * 8;
    const int ln0 = (wtid & 7) * 4;
    float* const hsp = pool + HS_OFF(kgrp);
    float* const wsp = pool + WS_OFF(kgrp);
    float* const pdst = (kgrp == 0) ? gsm : (pool + PART_OFF(kgrp));
    unsigned sense = g_sense;

    if (tid < 32) {
        int n = (tid >> 3) * Hz + jbase + (tid & 7);
        bsum1[tid] = bi1[tid >= 0 ? n : 0] + bh1[n];
    }
#pragma unroll
    for (int u = 0; u < 4; u++) ((float*)cs)[tid + u * 256] = 0.f;
    for (int idx = blockIdx.x * 256 + tid; idx < Bz * Hz; idx += NBLK * 256) {
        g_h0[0][idx] = 0.f;
        g_h1[0][idx] = 0.f;
    }
    grid_bar(sense);

    for (int t = 0; t < Tz; t++) {
        const int rb = t & 1, wb = rb ^ 1;

        // prefetch this step's g_pre values (consumed in L0 pointwise; latency
        // hidden behind the whole L0 GEMM)
        float pre[2][4];
#pragma unroll
        for (int u = 0; u < 2; u++) {
            int it = tid + u * 256;
            int b = it >> 3, jj = it & 7;
            const float* p = &g_pre[((size_t)(t * Bz + b)) * Gz + jbase + jj];
#pragma unroll
            for (int g = 0; g < 4; g++) pre[u][g] = p[g * Hz];
        }

        // ---------------- layer 0: gates = g_pre[t] + h0_prev @ Wh0^T ----------------
        ull acc[4][4];
#pragma unroll
        for (int bp = 0; bp < 4; bp++)
#pragma unroll
            for (int j = 0; j < 4; j++) acc[bp][j] = 0ull;
        gemm_ks(g_h0[rb], Wh0, jbase, wtid, kbase, acc, hsp, wsp);
        __syncthreads();                 // tiles dead -> safe to write partials
        store_part(pdst, b0, ln0, acc);
        __syncthreads();
#pragma unroll
        for (int u = 0; u < 9; u++) {    // reduce 4 partials into gsm (2304 floats)
            int i = tid + u * 256;
            gsm[i] += pool[PART_OFF(1) + i] + pool[PART_OFF(2) + i] + pool[PART_OFF(3) + i];
        }
        __syncthreads();
#pragma unroll
        for (int u = 0; u < 2; u++) {
            int it = tid + u * 256;           // (b, jj)
            int b = it >> 3, jj = it & 7;
            const float* g = &gsm[b * 36 + jj];
            float gi = g[0]  + pre[u][0];
            float gf = g[8]  + pre[u][1];
            float gg = g[16] + pre[u][2];
            float go = g[24] + pre[u][3];
            float c  = cs[0][it];
            float cn = sigm(gf) * c + sigm(gi) * tanhf(gg);
            float hn = sigm(go) * tanhf(cn);
            cs[0][it] = cn;
            g_h0[wb][b * Hz + jbase + jj] = hn;
            if (t == Tz - 1) {
                out[OUT_HOFF + b * Hz + jbase + jj] = hn;
                out[OUT_COFF + b * Hz + jbase + jj] = cn;
            }
        }
        grid_bar(sense);

        // ------- layer 1: gates = h0_cur @ Wi1^T + h1_prev @ Wh1^T + b1 -------
#pragma unroll
        for (int bp = 0; bp < 4; bp++)
#pragma unroll
            for (int j = 0; j < 4; j++) acc[bp][j] = 0ull;
        gemm_ks(g_h0[wb], Wi1, jbase, wtid, kbase, acc, hsp, wsp);  // current h0
        gemm_ks(g_h1[rb], Wh1, jbase, wtid, kbase, acc, hsp, wsp);  // previous h1
        __syncthreads();
        store_part(pdst, b0, ln0, acc);
        __syncthreads();
#pragma unroll
        for (int u = 0; u < 9; u++) {
            int i = tid + u * 256;
            gsm[i] += pool[PART_OFF(1) + i] + pool[PART_OFF(2) + i] + pool[PART_OFF(3) + i];
        }
        __syncthreads();
#pragma unroll
        for (int u = 0; u < 2; u++) {
            int it = tid + u * 256;
            int b = it >> 3, jj = it & 7;
            const float* g = &gsm[b * 36 + jj];
            float gi = g[0]  + bsum1[jj];
            float gf = g[8]  + bsum1[8 + jj];
            float gg = g[16] + bsum1[16 + jj];
            float go = g[24] + bsum1[24 + jj];
            float c  = cs[1][it];
            float cn = sigm(gf) * c + sigm(gi) * tanhf(gg);
            float hn = sigm(go) * tanhf(cn);
            cs[1][it] = cn;
            g_h1[wb][b * Hz + jbase + jj] = hn;
            out[(size_t)(b * Tz + t) * Hz + jbase + jj] = hn;   // top-layer output
            if (t == Tz - 1) {
                out[OUT_HOFF + Bz * Hz + b * Hz + jbase + jj] = hn;
                out[OUT_COFF + Bz * Hz + b * Hz + jbase + jj] = cn;
            }
        }
        grid_bar(sense);
    }
}

// ============================================================================
extern "C" void kernel_launch(void* const* d_in, const int* in_sizes, int n_in,
                              void* d_out, int out_size)
{
    const float* x   = (const float*)d_in[0];
    const float* Wi0 = (const float*)d_in[1];
    const float* Wh0 = (const float*)d_in[2];
    const float* bi0 = (const float*)d_in[3];
    const float* bh0 = (const float*)d_in[4];
    const float* Wi1 = (const float*)d_in[5];
    const float* Wh1 = (const float*)d_in[6];
    const float* bi1 = (const float*)d_in[7];
    const float* bh1 = (const float*)d_in[8];
    float* out = (float*)d_out;

    dim3 gpre(Gz / 128, (Bz * Tz) / 128);   // (32, 256)
    lstm_pre<<<gpre, 256>>>(x, Wi0, bi0, bh0);
    lstm_rec<<<NBLK, 256>>>(Wh0, Wi1, Wh1, bi1, bh1, out);
}

// round 9
// speedup vs baseline: 1.4365x; 1.0915x over previous
#include <cuda_runtime.h>

#define Bz 64
#define Tz 512
#define Fz 512
#define Hz 1024
#define Gz 4096   // 4*H
#define NBLK 128
#define NTH 512
#define OUT_HOFF (Bz*Tz*Hz)                 // 33,554,432
#define OUT_COFF (OUT_HOFF + 2*Bz*Hz)       // + 131,072

typedef unsigned long long ull;

// ---------------- static device scratch (no allocations allowed) ----------------
__device__ float g_pre[(size_t)Tz * Bz * Gz];   // [T][B][4H] input-GEMM + biases, 512MB
__device__ float g_h0[2][Bz * Hz];              // double-buffered layer0 h
__device__ float g_h1[2][Bz * Hz];              // double-buffered layer1 h
__device__ unsigned g_count;                    // grid barrier arrival counter
__device__ volatile unsigned g_sense;           // grid barrier monotonically-increasing sense

__device__ __forceinline__ float sigm(float x) { return 1.f / (1.f + __expf(-x)); }

// ---- packed fp32x2 FMA (sm_10x FFMA2; only reachable via PTX) ----
__device__ __forceinline__ void ffma2(ull &d, ull a, ull b) {
    asm("fma.rn.f32x2 %0, %1, %2, %0;" : "+l"(d) : "l"(a), "l"(b));
}
__device__ __forceinline__ ull pack2(float x, float y) {
    ull r; asm("mov.b64 %0, {%1, %2};" : "=l"(r) : "f"(x), "f"(y)); return r;
}
__device__ __forceinline__ ull dup2(float x) { return pack2(x, x); }
__device__ __forceinline__ float2 unpack2(ull v) {
    float2 r; asm("mov.b64 {%0, %1}, %2;" : "=f"(r.x), "=f"(r.y) : "l"(v)); return r;
}

// Grid-wide barrier. Grid=128 blocks <= SM count => all co-resident, no deadlock.
__device__ __forceinline__ void grid_bar(unsigned &sense) {
    __syncthreads();
    if (threadIdx.x == 0) {
        unsigned s = sense + 1u;
        sense = s;
        __threadfence();
        unsigned arr = atomicAdd(&g_count, 1u);
        if (arr == gridDim.x - 1) {
            g_count = 0;
            __threadfence();
            g_sense = s;
        } else {
            while (g_sense != s) { }
            __threadfence();
        }
    }
    __syncthreads();
}

// ============================================================================
// Phase A: g_pre[t][b][n] = sum_k x[b][t][k] * Wi0[n][k] + bi0[n] + bh0[n]
// (unchanged — ~2.5ms, not the bottleneck)
// ============================================================================
__global__ __launch_bounds__(256) void lstm_pre(
    const float* __restrict__ x, const float* __restrict__ Wi0,
    const float* __restrict__ bi0, const float* __restrict__ bh0)
{
    __shared__ float As[16][132];
    __shared__ float Bs[16][132];

    const int tid = threadIdx.x;
    const int n0 = blockIdx.x * 128;
    const int m0 = blockIdx.y * 128;
    const int ty = tid >> 4, tx = tid & 15;

    const int r0 = tid >> 2,          kq0 = tid & 3;
    const int r1 = (tid + 256) >> 2,  kq1 = (tid + 256) & 3;
    const int gr0 = m0 + r0, gr1 = m0 + r1;
    const float* xa0 = &x[((size_t)((gr0 & 63) * Tz + (gr0 >> 6))) * Fz + kq0 * 4];
    const float* xa1 = &x[((size_t)((gr1 & 63) * Tz + (gr1 >> 6))) * Fz + kq1 * 4];
    const float* wb0 = &Wi0[((size_t)(n0 + r0)) * Fz + kq0 * 4];
    const float* wb1 = &Wi0[((size_t)(n0 + r1)) * Fz + kq1 * 4];

    ull acc2[4][8];
#pragma unroll
    for (int p = 0; p < 4; p++)
#pragma unroll
        for (int j = 0; j < 8; j++) acc2[p][j] = 0ull;

    float4 pa0 = *(const float4*)xa0;
    float4 pa1 = *(const float4*)xa1;
    float4 pb0 = *(const float4*)wb0;
    float4 pb1 = *(const float4*)wb1;

    for (int kc = 0; kc < Fz / 16; kc++) {
        __syncthreads();
        As[kq0 * 4 + 0][r0] = pa0.x; As[kq0 * 4 + 1][r0] = pa0.y;
        As[kq0 * 4 + 2][r0] = pa0.z; As[kq0 * 4 + 3][r0] = pa0.w;
        As[kq1 * 4 + 0][r1] = pa1.x; As[kq1 * 4 + 1][r1] = pa1.y;
        As[kq1 * 4 + 2][r1] = pa1.z; As[kq1 * 4 + 3][r1] = pa1.w;
        Bs[kq0 * 4 + 0][r0] = pb0.x; Bs[kq0 * 4 + 1][r0] = pb0.y;
        Bs[kq0 * 4 + 2][r0] = pb0.z; Bs[kq0 * 4 + 3][r0] = pb0.w;
        Bs[kq1 * 4 + 0][r1] = pb1.x; Bs[kq1 * 4 + 1][r1] = pb1.y;
        Bs[kq1 * 4 + 2][r1] = pb1.z; Bs[kq1 * 4 + 3][r1] = pb1.w;
        __syncthreads();
        if (kc < Fz / 16 - 1) {
            int off = (kc + 1) * 16;
            pa0 = *(const float4*)(xa0 + off);
            pa1 = *(const float4*)(xa1 + off);
            pb0 = *(const float4*)(wb0 + off);
            pb1 = *(const float4*)(wb1 + off);
        }
#pragma unroll
        for (int kk = 0; kk < 16; kk++) {
            ulonglong2 a01 = *(const ulonglong2*)&As[kk][ty * 8];
            ulonglong2 a23 = *(const ulonglong2*)&As[kk][ty * 8 + 4];
            float bb[8];
            *(float4*)&bb[0] = *(const float4*)&Bs[kk][tx * 8];
            *(float4*)&bb[4] = *(const float4*)&Bs[kk][tx * 8 + 4];
#pragma unroll
            for (int j = 0; j < 8; j++) {
                ull wd = dup2(bb[j]);
                ffma2(acc2[0][j], a01.x, wd);
                ffma2(acc2[1][j], a01.y, wd);
                ffma2(acc2[2][j], a23.x, wd);
                ffma2(acc2[3][j], a23.y, wd);
            }
        }
    }

    float accf[8][8];
#pragma unroll
    for (int p = 0; p < 4; p++)
#pragma unroll
        for (int j = 0; j < 8; j++) {
            float2 v = unpack2(acc2[p][j]);
            accf[2 * p][j] = v.x;
            accf[2 * p + 1][j] = v.y;
        }

    float bsv[8];
#pragma unroll
    for (int j = 0; j < 8; j++) {
        int n = n0 + tx * 8 + j;
        bsv[j] = bi0[n] + bh0[n];
    }
#pragma unroll
    for (int i = 0; i < 8; i++) {
        size_t off = (size_t)(m0 + ty * 8 + i) * Gz + n0 + tx * 8;
        float4 v0, v1;
        v0.x = accf[i][0] + bsv[0]; v0.y = accf[i][1] + bsv[1];
        v0.z = accf[i][2] + bsv[2]; v0.w = accf[i][3] + bsv[3];
        v1.x = accf[i][4] + bsv[4]; v1.y = accf[i][5] + bsv[5];
        v1.z = accf[i][6] + bsv[6]; v1.w = accf[i][7] + bsv[7];
        *(float4*)&g_pre[off]     = v0;
        *(float4*)&g_pre[off + 4] = v1;
    }
}

// ============================================================================
// Persistent recurrent kernel, 512 threads = 8 k-groups x 64 threads.
// Each group: 64b x 32n tile over its K/8=128 slice, 8b x 4n micro-tile
// (f32x2 acc[4 b-pairs][4 n]). 1.5 SMEM bytes/FMA. 25% occupancy for latency
// hiding. Partials from 8 groups reduced in SMEM. Dynamic SMEM (~78KB).
// ============================================================================

// SMEM pool layout (floats), tile region and partial region are a union:
//   tiles:  hs[g] at g*1088 (16k x 68 floats), ws[g] at 8704 + g*576 (16k x 36)
//           total 13,312 floats
//   parts:  group g>=1 partial at (g-1)*2304 ([64][36]); group 0 -> gsm
//           total 16,128 floats  => pool = 16,128 floats
#define POOL_FLOATS 16128
#define HS_OFF(g)   ((g) * 1088)
#define WS_OFF(g)   (8704 + (g) * 576)
#define PART_OFF(g) (((g) - 1) * 2304)
#define SMEM_BYTES  ((POOL_FLOATS + 2304 + 1024 + 32) * 4)

__device__ __forceinline__ void gemm_ks(
    const float* __restrict__ hsrc,     // [B][H]
    const float* __restrict__ W,        // [4H][H] gate-row-major
    int jbase, int wtid, int kbase, ull (&acc)[4][4],
    float* __restrict__ hs, float* __restrict__ ws)
{
    const int b0  = (wtid >> 3) * 8;
    const int ln0 = (wtid & 7) * 4;

    // h staging: thread owns batch row b=wtid, loads 64B (16 k) per kc
    const float* hp = hsrc + (size_t)wtid * Hz + kbase;
    // w staging: 2 slots; idx = wtid + s*64 -> ln = idx>>2, kq = idx&3
    const float* wp[2];
    int wln[2], wkq[2];
#pragma unroll
    for (int s = 0; s < 2; s++) {
        int idx = wtid + s * 64;
        wln[s] = idx >> 2; wkq[s] = idx & 3;
        int row = (wln[s] >> 3) * Hz + jbase + (wln[s] & 7);
        wp[s] = W + (size_t)row * Hz + kbase + wkq[s] * 4;
    }

    float4 ph0 = *(const float4*)(hp);
    float4 ph1 = *(const float4*)(hp + 4);
    float4 ph2 = *(const float4*)(hp + 8);
    float4 ph3 = *(const float4*)(hp + 12);
    float4 pw0 = *(const float4*)wp[0];
    float4 pw1 = *(const float4*)wp[1];

    for (int kc = 0; kc < 8; kc++) {
        __syncthreads();        // previous tile fully consumed
        hs[ 0 * 68 + wtid] = ph0.x; hs[ 1 * 68 + wtid] = ph0.y;
        hs[ 2 * 68 + wtid] = ph0.z; hs[ 3 * 68 + wtid] = ph0.w;
        hs[ 4 * 68 + wtid] = ph1.x; hs[ 5 * 68 + wtid] = ph1.y;
        hs[ 6 * 68 + wtid] = ph1.z; hs[ 7 * 68 + wtid] = ph1.w;
        hs[ 8 * 68 + wtid] = ph2.x; hs[ 9 * 68 + wtid] = ph2.y;
        hs[10 * 68 + wtid] = ph2.z; hs[11 * 68 + wtid] = ph2.w;
        hs[12 * 68 + wtid] = ph3.x; hs[13 * 68 + wtid] = ph3.y;
        hs[14 * 68 + wtid] = ph3.z; hs[15 * 68 + wtid] = ph3.w;
        ws[(wkq[0] * 4 + 0) * 36 + wln[0]] = pw0.x;
        ws[(wkq[0] * 4 + 1) * 36 + wln[0]] = pw0.y;
        ws[(wkq[0] * 4 + 2) * 36 + wln[0]] = pw0.z;
        ws[(wkq[0] * 4 + 3) * 36 + wln[0]] = pw0.w;
        ws[(wkq[1] * 4 + 0) * 36 + wln[1]] = pw1.x;
        ws[(wkq[1] * 4 + 1) * 36 + wln[1]] = pw1.y;
        ws[(wkq[1] * 4 + 2) * 36 + wln[1]] = pw1.z;
        ws[(wkq[1] * 4 + 3) * 36 + wln[1]] = pw1.w;
        __syncthreads();
        if (kc < 7) {           // prefetch next tile into regs (overlaps compute)
            int off = (kc + 1) * 16;
            ph0 = *(const float4*)(hp + off);
            ph1 = *(const float4*)(hp + off + 4);
            ph2 = *(const float4*)(hp + off + 8);
            ph3 = *(const float4*)(hp + off + 12);
            pw0 = *(const float4*)(wp[0] + off);
            pw1 = *(const float4*)(wp[1] + off);
        }
#pragma unroll 4
        for (int kk = 0; kk < 16; kk++) {
            const float* hrow = hs + kk * 68 + b0;
            ulonglong2 hA = *(const ulonglong2*)(hrow);      // b-pairs (0,1),(2,3)
            ulonglong2 hB = *(const ulonglong2*)(hrow + 4);  // b-pairs (4,5),(6,7)
            float4 wv = *(const float4*)(ws + kk * 36 + ln0);
            ull w0 = dup2(wv.x), w1 = dup2(wv.y), w2 = dup2(wv.z), w3 = dup2(wv.w);
            ffma2(acc[0][0], hA.x, w0); ffma2(acc[1][0], hA.y, w0);
            ffma2(acc[2][0], hB.x, w0); ffma2(acc[3][0], hB.y, w0);
            ffma2(acc[0][1], hA.x, w1); ffma2(acc[1][1], hA.y, w1);
            ffma2(acc[2][1], hB.x, w1); ffma2(acc[3][1], hB.y, w1);
            ffma2(acc[0][2], hA.x, w2); ffma2(acc[1][2], hA.y, w2);
            ffma2(acc[2][2], hB.x, w2); ffma2(acc[3][2], hB.y, w2);
            ffma2(acc[0][3], hA.x, w3); ffma2(acc[1][3], hA.y, w3);
            ffma2(acc[2][3], hB.x, w3); ffma2(acc[3][3], hB.y, w3);
        }
    }
}

// Unpack f32x2 accumulators into a [64][36] partial buffer (float4 rows).
__device__ __forceinline__ void store_part(float* __restrict__ dst,
                                           int b0, int ln0, ull (&acc)[4][4])
{
#pragma unroll
    for (int bp = 0; bp < 4; bp++) {
        float2 v0 = unpack2(acc[bp][0]);
        float2 v1 = unpack2(acc[bp][1]);
        float2 v2 = unpack2(acc[bp][2]);
        float2 v3 = unpack2(acc[bp][3]);
        float4 lo, hi;
        lo.x = v0.x; lo.y = v1.x; lo.z = v2.x; lo.w = v3.x;
        hi.x = v0.y; hi.y = v1.y; hi.z = v2.y; hi.w = v3.y;
        *(float4*)&dst[(b0 + 2 * bp) * 36 + ln0]     = lo;
        *(float4*)&dst[(b0 + 2 * bp + 1) * 36 + ln0] = hi;
    }
}

__global__ __launch_bounds__(NTH) void lstm_rec(
    const float* __restrict__ Wh0, const float* __restrict__ Wi1,
    const float* __restrict__ Wh1, const float* __restrict__ bi1,
    const float* __restrict__ bh1, float* __restrict__ out)
{
    extern __shared__ __align__(16) float smem[];
    float* const pool  = smem;                         // 16,128 floats (union)
    float* const gsm   = smem + POOL_FLOATS;           // 2,304 (grp0 partial + reduced)
    float* const cs    = smem + POOL_FLOATS + 2304;    // 1,024 (2 layers x 512)
    float* const bsum1 = smem + POOL_FLOATS + 2304 + 1024;  // 32

    const int tid = threadIdx.x;
    const int jbase = blockIdx.x * 8;
    const int kgrp = tid >> 6;
    const int wtid = tid & 63;
    const int kbase = kgrp * 128;
    const int b0  = (wtid >> 3) * 8;
    const int ln0 = (wtid & 7) * 4;
    const int pb = tid >> 3, pj = tid & 7;    // pointwise item (b, jj)
    float* const hsp = pool + HS_OFF(kgrp);
    float* const wsp = pool + WS_OFF(kgrp);
    float* const pdst = (kgrp == 0) ? gsm : (pool + PART_OFF(kgrp));
    unsigned sense = g_sense;

    if (tid < 32) {
        int n = (tid >> 3) * Hz + jbase + (tid & 7);
        bsum1[tid] = bi1[n] + bh1[n];
    }
    cs[tid] = 0.f;
    cs[tid + 512] = 0.f;
    for (int idx = blockIdx.x * NTH + tid; idx < Bz * Hz; idx += NBLK * NTH) {
        g_h0[0][idx] = 0.f;
        g_h1[0][idx] = 0.f;
    }
    grid_bar(sense);

    for (int t = 0; t < Tz; t++) {
        const int rb = t & 1, wb = rb ^ 1;

        // prefetch this step's g_pre values (consumed in L0 pointwise;
        // latency hidden behind the whole L0 GEMM)
        float pre[4];
        {
            const float* p = &g_pre[((size_t)(t * Bz + pb)) * Gz + jbase + pj];
#pragma unroll
            for (int g = 0; g < 4; g++) pre[g] = p[g * Hz];
        }

        // ---------------- layer 0: gates = g_pre[t] + h0_prev @ Wh0^T ----------------
        ull acc[4][4];
#pragma unroll
        for (int bp = 0; bp < 4; bp++)
#pragma unroll
            for (int j = 0; j < 4; j++) acc[bp][j] = 0ull;
        gemm_ks(g_h0[rb], Wh0, jbase, wtid, kbase, acc, hsp, wsp);
        __syncthreads();                 // tiles dead -> safe to write partials
        store_part(pdst, b0, ln0, acc);
        __syncthreads();
        for (int i = tid; i < 2304; i += NTH) {   // reduce 8 partials into gsm
            float v = gsm[i];
#pragma unroll
            for (int g = 1; g < 8; g++) v += pool[PART_OFF(g) + i];
            gsm[i] = v;
        }
        __syncthreads();
        {
            const float* g = &gsm[pb * 36 + pj];
            float gi = g[0]  + pre[0];
            float gf = g[8]  + pre[1];
            float gg = g[16] + pre[2];
            float go = g[24] + pre[3];
            float c  = cs[tid];
            float cn = sigm(gf) * c + sigm(gi) * tanhf(gg);
            float hn = sigm(go) * tanhf(cn);
            cs[tid] = cn;
            g_h0[wb][pb * Hz + jbase + pj] = hn;
            if (t == Tz - 1) {
                out[OUT_HOFF + pb * Hz + jbase + pj] = hn;
                out[OUT_COFF + pb * Hz + jbase + pj] = cn;
            }
        }
        grid_bar(sense);

        // ------- layer 1: gates = h0_cur @ Wi1^T + h1_prev @ Wh1^T + b1 -------
#pragma unroll
        for (int bp = 0; bp < 4; bp++)
#pragma unroll
            for (int j = 0; j < 4; j++) acc[bp][j] = 0ull;
        gemm_ks(g_h0[wb], Wi1, jbase, wtid, kbase, acc, hsp, wsp);  // current h0
        gemm_ks(g_h1[rb], Wh1, jbase, wtid, kbase, acc, hsp, wsp);  // previous h1
        __syncthreads();
        store_part(pdst, b0, ln0, acc);
        __syncthreads();
        for (int i = tid; i < 2304; i += NTH) {
            float v = gsm[i];
#pragma unroll
            for (int g = 1; g < 8; g++) v += pool[PART_OFF(g) + i];
            gsm[i] = v;
        }
        __syncthreads();
        {
            const float* g = &gsm[pb * 36 + pj];
            float gi = g[0]  + bsum1[pj];
            float gf = g[8]  + bsum1[8 + pj];
            float gg = g[16] + bsum1[16 + pj];
            float go = g[24] + bsum1[24 + pj];
            float c  = cs[512 + tid];
            float cn = sigm(gf) * c + sigm(gi) * tanhf(gg);
            float hn = sigm(go) * tanhf(cn);
            cs[512 + tid] = cn;
            g_h1[wb][pb * Hz + jbase + pj] = hn;
            out[(size_t)(pb * Tz + t) * Hz + jbase + pj] = hn;   // top-layer output
            if (t == Tz - 1) {
                out[OUT_HOFF + Bz * Hz + pb * Hz + jbase + pj] = hn;
                out[OUT_COFF + Bz * Hz + pb * Hz + jbase + pj] = cn;
            }
        }
        grid_bar(sense);
    }
}

// ============================================================================
extern "C" void kernel_launch(void* const* d_in, const int* in_sizes, int n_in,
                              void* d_out, int out_size)
{
    const float* x   = (const float*)d_in[0];
    const float* Wi0 = (const float*)d_in[1];
    const float* Wh0 = (const float*)d_in[2];
    const float* bi0 = (const float*)d_in[3];
    const float* bh0 = (const float*)d_in[4];
    const float* Wi1 = (const float*)d_in[5];
    const float* Wh1 = (const float*)d_in[6];
    const float* bi1 = (const float*)d_in[7];
    const float* bh1 = (const float*)d_in[8];
    float* out = (float*)d_out;

    // raise dynamic SMEM cap (idempotent; not an allocation)
    static int smem_set = 0;
    if (!smem_set) {
        cudaFuncSetAttribute(lstm_rec, cudaFuncAttributeMaxDynamicSharedMemorySize,
                             SMEM_BYTES);
        smem_set = 1;
    }

    dim3 gpre(Gz / 128, (Bz * Tz) / 128);   // (32, 256)
    lstm_pre<<<gpre, 256>>>(x, Wi0, bi0, bh0);
    lstm_rec<<<NBLK, NTH, SMEM_BYTES>>>(Wh0, Wi1, Wh1, bi1, bh1, out);
}

// round 12
// speedup vs baseline: 2.0309x; 1.4139x over previous
#include <cuda_runtime.h>

#define Bz 64
#define Tz 512
#define Fz 512
#define Hz 1024
#define Gz 4096   // 4*H
#define NBLK 128
#define NTH 512
#define OUT_HOFF (Bz*Tz*Hz)                 // 33,554,432
#define OUT_COFF (OUT_HOFF + 2*Bz*Hz)       // + 131,072

typedef unsigned long long ull;

// ---------------- static device scratch (no allocations allowed) ----------------
__device__ float g_pre[(size_t)Tz * Bz * Gz];       // [T][B][4H] input-GEMM + biases
__device__ float g_WT[3][(size_t)NBLK * Hz * 32];   // transposed weights: [jblk][k][32 ln], 48MB
__device__ float g_h0T[2][Hz * Bz];                 // layer0 h, TRANSPOSED [k][b]
__device__ float g_h1T[2][Hz * Bz];                 // layer1 h, TRANSPOSED [k][b]
__device__ unsigned g_count;
__device__ volatile unsigned g_sense;

__device__ __forceinline__ float sigm(float x) { return 1.f / (1.f + __expf(-x)); }

// ---- packed fp32x2 FMA (sm_10x FFMA2; only reachable via PTX) ----
__device__ __forceinline__ void ffma2(ull &d, ull a, ull b) {
    asm("fma.rn.f32x2 %0, %1, %2, %0;" : "+l"(d) : "l"(a), "l"(b));
}
__device__ __forceinline__ ull pack2(float x, float y) {
    ull r; asm("mov.b64 %0, {%1, %2};" : "=l"(r) : "f"(x), "f"(y)); return r;
}
__device__ __forceinline__ ull dup2(float x) { return pack2(x, x); }
__device__ __forceinline__ float2 unpack2(ull v) {
    float2 r; asm("mov.b64 {%0, %1}, %2;" : "=f"(r.x), "=f"(r.y) : "l"(v)); return r;
}

// Grid-wide barrier. Grid=128 blocks <= SM count => all co-resident, no deadlock.
__device__ __forceinline__ void grid_bar(unsigned &sense) {
    __syncthreads();
    if (threadIdx.x == 0) {
        unsigned s = sense + 1u;
        sense = s;
        __threadfence();
        unsigned arr = atomicAdd(&g_count, 1u);
        if (arr == gridDim.x - 1) {
            g_count = 0;
            __threadfence();
            g_sense = s;
        } else {
            while (g_sense != s) { }
            __threadfence();
        }
    }
    __syncthreads();
}

// ============================================================================
// Weight pre-transpose: g_WT[m][jblk][k][ln] = W[(ln>>3)*H + jblk*8 + (ln&7)][k]
// 32x32 SMEM tile transpose, both sides coalesced. Grid (128, 32, 3), 256 thr.
// ============================================================================
__global__ __launch_bounds__(256) void lstm_wt(
    const float* __restrict__ W0, const float* __restrict__ W1,
    const float* __restrict__ W2)
{
    __shared__ float tile[32][33];
    const int jblk = blockIdx.x;
    const int k0   = blockIdx.y * 32;
    const int m    = blockIdx.z;
    const float* W = (m == 0) ? W0 : (m == 1) ? W1 : W2;
    float* dst = g_WT[m];
    const int lane = threadIdx.x & 31, grp = threadIdx.x >> 5;
#pragma unroll
    for (int i = 0; i < 4; i++) {
        int ln = grp + i * 8;
        int row = (ln >> 3) * Hz + jblk * 8 + (ln & 7);
        tile[ln][lane] = W[(size_t)row * Hz + k0 + lane];   // coalesced over k
    }
    __syncthreads();
#pragma unroll
    for (int i = 0; i < 4; i++) {
        int k = grp + i * 8;
        dst[((size_t)jblk * Hz + k0 + k) * 32 + lane] = tile[lane][k];  // coalesced over ln
    }
}

// ============================================================================
// Phase A: g_pre[t][b][n] = sum_k x[b][t][k] * Wi0[n][k] + bi0[n] + bh0[n]
// (unchanged — ~2.5ms, not the bottleneck)
// ============================================================================
__global__ __launch_bounds__(256) void lstm_pre(
    const float* __restrict__ x, const float* __restrict__ Wi0,
    const float* __restrict__ bi0, const float* __restrict__ bh0)
{
    __shared__ float As[16][132];
    __shared__ float Bs[16][132];

    const int tid = threadIdx.x;
    const int n0 = blockIdx.x * 128;
    const int m0 = blockIdx.y * 128;
    const int ty = tid >> 4, tx = tid & 15;

    const int r0 = tid >> 2,          kq0 = tid & 3;
    const int r1 = (tid + 256) >> 2,  kq1 = (tid + 256) & 3;
    const int gr0 = m0 + r0, gr1 = m0 + r1;
    const float* xa0 = &x[((size_t)((gr0 & 63) * Tz + (gr0 >> 6))) * Fz + kq0 * 4];
    const float* xa1 = &x[((size_t)((gr1 & 63) * Tz + (gr1 >> 6))) * Fz + kq1 * 4];
    const float* wb0 = &Wi0[((size_t)(n0 + r0)) * Fz + kq0 * 4];
    const float* wb1 = &Wi0[((size_t)(n0 + r1)) * Fz + kq1 * 4];

    ull acc2[4][8];
#pragma unroll
    for (int p = 0; p < 4; p++)
#pragma unroll
        for (int j = 0; j < 8; j++) acc2[p][j] = 0ull;

    float4 pa0 = *(const float4*)xa0;
    float4 pa1 = *(const float4*)xa1;
    float4 pb0 = *(const float4*)wb0;
    float4 pb1 = *(const float4*)wb1;

    for (int kc = 0; kc < Fz / 16; kc++) {
        __syncthreads();
        As[kq0 * 4 + 0][r0] = pa0.x; As[kq0 * 4 + 1][r0] = pa0.y;
        As[kq0 * 4 + 2][r0] = pa0.z; As[kq0 * 4 + 3][r0] = pa0.w;
        As[kq1 * 4 + 0][r1] = pa1.x; As[kq1 * 4 + 1][r1] = pa1.y;
        As[kq1 * 4 + 2][r1] = pa1.z; As[kq1 * 4 + 3][r1] = pa1.w;
        Bs[kq0 * 4 + 0][r0] = pb0.x; Bs[kq0 * 4 + 1][r0] = pb0.y;
        Bs[kq0 * 4 + 2][r0] = pb0.z; Bs[kq0 * 4 + 3][r0] = pb0.w;
        Bs[kq1 * 4 + 0][r1] = pb1.x; Bs[kq1 * 4 + 1][r1] = pb1.y;
        Bs[kq1 * 4 + 2][r1] = pb1.z; Bs[kq1 * 4 + 3][r1] = pb1.w;
        __syncthreads();
        if (kc < Fz / 16 - 1) {
            int off = (kc + 1) * 16;
            pa0 = *(const float4*)(xa0 + off);
            pa1 = *(const float4*)(xa1 + off);
            pb0 = *(const float4*)(wb0 + off);
            pb1 = *(const float4*)(wb1 + off);
        }
#pragma unroll
        for (int kk = 0; kk < 16; kk++) {
            ulonglong2 a01 = *(const ulonglong2*)&As[kk][ty * 8];
            ulonglong2 a23 = *(const ulonglong2*)&As[kk][ty * 8 + 4];
            float bb[8];
            *(float4*)&bb[0] = *(const float4*)&Bs[kk][tx * 8];
            *(float4*)&bb[4] = *(const float4*)&Bs[kk][tx * 8 + 4];
#pragma unroll
            for (int j = 0; j < 8; j++) {
                ull wd = dup2(bb[j]);
                ffma2(acc2[0][j], a01.x, wd);
                ffma2(acc2[1][j], a01.y, wd);
                ffma2(acc2[2][j], a23.x, wd);
                ffma2(acc2[3][j], a23.y, wd);
            }
        }
    }

    float accf[8][8];
#pragma unroll
    for (int p = 0; p < 4; p++)
#pragma unroll
        for (int j = 0; j < 8; j++) {
            float2 v = unpack2(acc2[p][j]);
            accf[2 * p][j] = v.x;
            accf[2 * p + 1][j] = v.y;
        }

    float bsv[8];
#pragma unroll
    for (int j = 0; j < 8; j++) {
        int n = n0 + tx * 8 + j;
        bsv[j] = bi0[n] + bh0[n];
    }
#pragma unroll
    for (int i = 0; i < 8; i++) {
        size_t off = (size_t)(m0 + ty * 8 + i) * Gz + n0 + tx * 8;
        float4 v0, v1;
        v0.x = accf[i][0] + bsv[0]; v0.y = accf[i][1] + bsv[1];
        v0.z = accf[i][2] + bsv[2]; v0.w = accf[i][3] + bsv[3];
        v1.x = accf[i][4] + bsv[4]; v1.y = accf[i][5] + bsv[5];
        v1.z = accf[i][6] + bsv[6]; v1.w = accf[i][7] + bsv[7];
        *(float4*)&g_pre[off]     = v0;
        *(float4*)&g_pre[off + 4] = v1;
    }
}

// ============================================================================
// Persistent recurrent kernel, 512 threads = 8 k-groups x 64 threads.
// All global layouts k-major => every staging access is an IDENTITY memcpy:
//   h tile:  4KB contiguous from g_hT (16k x 64b), float4 coalesced both sides
//   w tile:  2KB contiguous from g_WT (16k x 32ln)
// Micro-tile 8b x 4n in f32x2. Partials from 8 groups reduced in SMEM.
// ============================================================================

// SMEM pool (floats): tiles (hs[g] 1024 + ws[g] 512 at g*1536; 12,288 total)
// union with partials (g>=1 at (g-1)*2304; 16,128 total) => pool = 16,128
#define POOL_FLOATS 16128
#define HS_OFF(g)   ((g) * 1536)
#define WS_OFF(g)   ((g) * 1536 + 1024)
#define PART_OFF(g) (((g) - 1) * 2304)
#define SMEM_BYTES  ((POOL_FLOATS + 2304 + 1024 + 32) * 4)

__device__ __forceinline__ void gemm_ks(
    const float* __restrict__ hT,   // group's h slice: [(128k) x 64b] contiguous
    const float* __restrict__ WT,   // group's w slice: [(128k) x 32ln] contiguous
    int wtid, ull (&acc)[4][4],
    float* __restrict__ hs, float* __restrict__ ws)
{
    const int b0  = (wtid >> 3) * 8;
    const int ln0 = (wtid & 7) * 4;
    const int h4  = wtid * 4;

    float4 ph0 = *(const float4*)(hT + h4);
    float4 ph1 = *(const float4*)(hT + 256 + h4);
    float4 ph2 = *(const float4*)(hT + 512 + h4);
    float4 ph3 = *(const float4*)(hT + 768 + h4);
    float4 pw0 = *(const float4*)(WT + h4);
    float4 pw1 = *(const float4*)(WT + 256 + h4);

    for (int kc = 0; kc < 8; kc++) {
        __syncthreads();        // previous tile fully consumed
        *(float4*)(hs + h4)       = ph0;
        *(float4*)(hs + 256 + h4) = ph1;
        *(float4*)(hs + 512 + h4) = ph2;
        *(float4*)(hs + 768 + h4) = ph3;
        *(float4*)(ws + h4)       = pw0;
        *(float4*)(ws + 256 + h4) = pw1;
        __syncthreads();
        if (kc < 7) {           // prefetch next tile (latency overlaps compute)
            const float* hn = hT + (kc + 1) * 1024;
            const float* wn = WT + (kc + 1) * 512;
            ph0 = *(const float4*)(hn + h4);
            ph1 = *(const float4*)(hn + 256 + h4);
            ph2 = *(const float4*)(hn + 512 + h4);
            ph3 = *(const float4*)(hn + 768 + h4);
            pw0 = *(const float4*)(wn + h4);
            pw1 = *(const float4*)(wn + 256 + h4);
        }
#pragma unroll 4
        for (int kk = 0; kk < 16; kk++) {
            const float* hrow = hs + kk * 64 + b0;
            ulonglong2 hA = *(const ulonglong2*)(hrow);      // b-pairs (0,1),(2,3)
            ulonglong2 hB = *(const ulonglong2*)(hrow + 4);  // b-pairs (4,5),(6,7)
            float4 wv = *(const float4*)(ws + kk * 32 + ln0);
            ull w0 = dup2(wv.x), w1 = dup2(wv.y), w2 = dup2(wv.z), w3 = dup2(wv.w);
            ffma2(acc[0][0], hA.x, w0); ffma2(acc[1][0], hA.y, w0);
            ffma2(acc[2][0], hB.x, w0); ffma2(acc[3][0], hB.y, w0);
            ffma2(acc[0][1], hA.x, w1); ffma2(acc[1][1], hA.y, w1);
            ffma2(acc[2][1], hB.x, w1); ffma2(acc[3][1], hB.y, w1);
            ffma2(acc[0][2], hA.x, w2); ffma2(acc[1][2], hA.y, w2);
            ffma2(acc[2][2], hB.x, w2); ffma2(acc[3][2], hB.y, w2);
            ffma2(acc[0][3], hA.x, w3); ffma2(acc[1][3], hA.y, w3);
            ffma2(acc[2][3], hB.x, w3); ffma2(acc[3][3], hB.y, w3);
        }
    }
}

// Unpack f32x2 accumulators into a [64][36] partial buffer (float4 rows).
__device__ __forceinline__ void store_part(float* __restrict__ dst,
                                           int b0, int ln0, ull (&acc)[4][4])
{
#pragma unroll
    for (int bp = 0; bp < 4; bp++) {
        float2 v0 = unpack2(acc[bp][0]);
        float2 v1 = unpack2(acc[bp][1]);
        float2 v2 = unpack2(acc[bp][2]);
        float2 v3 = unpack2(acc[bp][3]);
        float4 lo, hi;
        lo.x = v0.x; lo.y = v1.x; lo.z = v2.x; lo.w = v3.x;
        hi.x = v0.y; hi.y = v1.y; hi.z = v2.y; hi.w = v3.y;
        *(float4*)&dst[(b0 + 2 * bp) * 36 + ln0]     = lo;
        *(float4*)&dst[(b0 + 2 * bp + 1) * 36 + ln0] = hi;
    }
}

__global__ __launch_bounds__(NTH) void lstm_rec(
    const float* __restrict__ bi1, const float* __restrict__ bh1,
    float* __restrict__ out)
{
    extern __shared__ __align__(16) float smem[];
    float* const pool  = smem;                              // 16,128 (union)
    float* const gsm   = smem + POOL_FLOATS;                // 2,304
    float* const cs    = smem + POOL_FLOATS + 2304;         // 1,024
    float* const bsum1 = smem + POOL_FLOATS + 2304 + 1024;  // 32

    const int tid = threadIdx.x;
    const int jbase = blockIdx.x * 8;
    const int kgrp = tid >> 6;
    const int wtid = tid & 63;
    const int kbase = kgrp * 128;
    const int b0  = (wtid >> 3) * 8;
    const int ln0 = (wtid & 7) * 4;
    const int pb = tid >> 3, pj = tid & 7;    // pointwise item (b, jj)
    float* const hsp = pool + HS_OFF(kgrp);
    float* const wsp = pool + WS_OFF(kgrp);
    float* const pdst = (kgrp == 0) ? gsm : (pool + PART_OFF(kgrp));
    // per-group slice bases (k-major layouts)
    const size_t hoff = (size_t)kbase * Bz;
    const size_t woff = ((size_t)blockIdx.x * Hz + kbase) * 32;
    const float* const WT0 = g_WT[0] + woff;   // Wh0
    const float* const WT1 = g_WT[1] + woff;   // Wi1
    const float* const WT2 = g_WT[2] + woff;   // Wh1
    unsigned sense = g_sense;

    if (tid < 32) {
        int n = (tid >> 3) * Hz + jbase + (tid & 7);
        bsum1[tid] = bi1[n] + bh1[n];
    }
    cs[tid] = 0.f;
    cs[tid + 512] = 0.f;
    for (int idx = blockIdx.x * NTH + tid; idx < Bz * Hz; idx += NBLK * NTH) {
        g_h0T[0][idx] = 0.f;
        g_h1T[0][idx] = 0.f;
    }
    grid_bar(sense);

    for (int t = 0; t < Tz; t++) {
        const int rb = t & 1, wb = rb ^ 1;

        // prefetch this step's g_pre values (consumed in L0 pointwise;
        // latency hidden behind the whole L0 GEMM)
        float pre[4];
        {
            const float* p = &g_pre[((size_t)(t * Bz + pb)) * Gz + jbase + pj];
#pragma unroll
            for (int g = 0; g < 4; g++) pre[g] = p[g * Hz];
        }

        // ---------------- layer 0: gates = g_pre[t] + h0_prev @ Wh0^T ----------------
        ull acc[4][4];
#pragma unroll
        for (int bp = 0; bp < 4; bp++)
#pragma unroll
            for (int j = 0; j < 4; j++) acc[bp][j] = 0ull;
        gemm_ks(g_h0T[rb] + hoff, WT0, wtid, acc, hsp, wsp);
        __syncthreads();                 // tiles dead -> safe to write partials
        store_part(pdst, b0, ln0, acc);
        __syncthreads();
        for (int i = tid; i < 2304; i += NTH) {   // reduce 8 partials into gsm
            float v = gsm[i];
#pragma unroll
            for (int g = 1; g < 8; g++) v += pool[PART_OFF(g) + i];
            gsm[i] = v;
        }
        __syncthreads();
        {
            const float* g = &gsm[pb * 36 + pj];
            float gi = g[0]  + pre[0];
            float gf = g[8]  + pre[1];
            float gg = g[16] + pre[2];
            float go = g[24] + pre[3];
            float c  = cs[tid];
            float cn = sigm(gf) * c + sigm(gi) * tanhf(gg);
            float hn = sigm(go) * tanhf(cn);
            cs[tid] = cn;
            g_h0T[wb][(jbase + pj) * Bz + pb] = hn;   // transposed write
            if (t == Tz - 1) {
                out[OUT_HOFF + pb * Hz + jbase + pj] = hn;
                out[OUT_COFF + pb * Hz + jbase + pj] = cn;
            }
        }
        grid_bar(sense);

        // ------- layer 1: gates = h0_cur @ Wi1^T + h1_prev @ Wh1^T + b1 -------
#pragma unroll
        for (int bp = 0; bp < 4; bp++)
#pragma unroll
            for (int j = 0; j < 4; j++) acc[bp][j] = 0ull;
        gemm_ks(g_h0T[wb] + hoff, WT1, wtid, acc, hsp, wsp);  // current h0
        gemm_ks(g_h1T[rb] + hoff, WT2, wtid, acc, hsp, wsp);  // previous h1
        __syncthreads();
        store_part(pdst, b0, ln0, acc);
        __syncthreads();
        for (int i = tid; i < 2304; i += NTH) {
            float v = gsm[i];
#pragma unroll
            for (int g = 1; g < 8; g++) v += pool[PART_OFF(g) + i];
            gsm[i] = v;
        }
        __syncthreads();
        {
            const float* g = &gsm[pb * 36 + pj];
            float gi = g[0]  + bsum1[pj];
            float gf = g[8]  + bsum1[8 + pj];
            float gg = g[16] + bsum1[16 + pj];
            float go = g[24] + bsum1[24 + pj];
            float c  = cs[512 + tid];
            float cn = sigm(gf) * c + sigm(gi) * tanhf(gg);
            float hn = sigm(go) * tanhf(cn);
            cs[512 + tid] = cn;
            g_h1T[wb][(jbase + pj) * Bz + pb] = hn;   // transposed write
            out[(size_t)(pb * Tz + t) * Hz + jbase + pj] = hn;   // top-layer output
            if (t == Tz - 1) {
                out[OUT_HOFF + Bz * Hz + pb * Hz + jbase + pj] = hn;
                out[OUT_COFF + Bz * Hz + pb * Hz + jbase + pj] = cn;
            }
        }
        grid_bar(sense);
    }
}

// ============================================================================
extern "C" void kernel_launch(void* const* d_in, const int* in_sizes, int n_in,
                              void* d_out, int out_size)
{
    const float* x   = (const float*)d_in[0];
    const float* Wi0 = (const float*)d_in[1];
    const float* Wh0 = (const float*)d_in[2];
    const float* bi0 = (const float*)d_in[3];
    const float* bh0 = (const float*)d_in[4];
    const float* Wi1 = (const float*)d_in[5];
    const float* Wh1 = (const float*)d_in[6];
    const float* bi1 = (const float*)d_in[7];
    const float* bh1 = (const float*)d_in[8];
    float* out = (float*)d_out;

    // raise dynamic SMEM cap (idempotent; not an allocation)
    static int smem_set = 0;
    if (!smem_set) {
        cudaFuncSetAttribute(lstm_rec, cudaFuncAttributeMaxDynamicSharedMemorySize,
                             SMEM_BYTES);
        smem_set = 1;
    }

    dim3 gwt(NBLK, Hz / 32, 3);             // weight transpose (stream-ordered)
    lstm_wt<<<gwt, 256>>>(Wh0, Wi1, Wh1);
    dim3 gpre(Gz / 128, (Bz * Tz) / 128);   // (32, 256)
    lstm_pre<<<gpre, 256>>>(x, Wi0, bi0, bh0);
    lstm_rec<<<NBLK, NTH, SMEM_BYTES>>>(bi1, bh1, out);
}